// round 2
// baseline (speedup 1.0000x reference)
#include <cuda_runtime.h>
#include <math.h>

#define BN 16
#define UPD 512
#define NPIX (UPD*UPD)
#define PATCH 120
#define NM 4

// ---------------- static device scratch (no runtime allocation) ----------------
__device__ float g_inv[3*BN*6];                 // inverse thetas: [which][b][6]
__device__ float g_bufA[BN*NPIX];               // pred_trans
__device__ float g_bufB[BN*NPIX];               // pred_rot
__device__ float g_rm2[NM*BN*NPIX];             // mask after g2 sample
__device__ unsigned g_bits[NM*BN*NPIX/32];      // packed masks_rot bits
__device__ float g_part1[NM*BN*64*2];           // partial sums (new, mask)
__device__ float g_part3[NM*BN*64*3];           // partial sums (tot, sx, sy)
__device__ float g_thr[NM*BN];                  // per (j,b) threshold
__device__ float g_patch[BN*PATCH*PATCH];       // revise patch snapshot

// ---------------- helpers ----------------
__device__ __forceinline__ float bilin_sample(const float* __restrict__ s,
                                              float gx, float gy, int H, int W) {
    // torch grid_sample: bilinear, zero padding, align_corners=False
    float x = ((gx + 1.0f) * (float)W - 1.0f) * 0.5f;
    float y = ((gy + 1.0f) * (float)H - 1.0f) * 0.5f;
    float xf = floorf(x), yf = floorf(y);
    int x0 = (int)xf, y0 = (int)yf;
    float wx = x - xf, wy = y - yf;
    int x1 = x0 + 1, y1 = y0 + 1;
    bool xi0 = (x0 >= 0) && (x0 < W);
    bool xi1 = (x1 >= 0) && (x1 < W);
    bool yi0 = (y0 >= 0) && (y0 < H);
    bool yi1 = (y1 >= 0) && (y1 < H);
    float v00 = 0.f, v01 = 0.f, v10 = 0.f, v11 = 0.f;
    if (yi0) {
        const float* row = s + y0 * W;
        if (xi0) v00 = __ldg(row + x0);
        if (xi1) v01 = __ldg(row + x1);
    }
    if (yi1) {
        const float* row = s + y1 * W;
        if (xi0) v10 = __ldg(row + x0);
        if (xi1) v11 = __ldg(row + x1);
    }
    return (1.f - wx) * (1.f - wy) * v00 + wx * (1.f - wy) * v01
         + (1.f - wx) * wy * v10 + wx * wy * v11;
}

// ---------------- K0: 2x3 affine inverses ----------------
__global__ void k_inv(const float* __restrict__ sc, const float* __restrict__ ro,
                      const float* __restrict__ tr) {
    int t = threadIdx.x;
    if (t >= 3 * BN) return;
    int w = t / BN, b = t % BN;
    const float* src = (w == 0) ? sc : ((w == 1) ? ro : tr);
    const float* m = src + b * 6;
    float a = m[0], bb = m[1], c = m[2], d = m[3], e = m[4], f = m[5];
    float det = a * e - bb * d;
    float ia = e / det, ib = -bb / det, id = -d / det, ie = a / det;
    float ic  = -(ia * c + ib * f);
    float iff = -(id * c + ie * f);
    float* o = g_inv + t * 6;
    o[0] = ia; o[1] = ib; o[2] = ic; o[3] = id; o[4] = ie; o[5] = iff;
}

// ---------------- K1: jax.image.resize linear, 4 outputs/thread ----------------
__global__ void k_resize4(const float* __restrict__ base, float* __restrict__ out) {
    int idx = blockIdx.x * blockDim.x + threadIdx.x;
    if (idx >= BN * NPIX / 4) return;
    int b = idx / (NPIX / 4), r4 = idx - b * (NPIX / 4);
    int i = r4 >> 7;
    int j0 = (r4 & 127) * 4;
    float fy = (i + 0.5f) * 0.25f - 0.5f;
    fy = fminf(fmaxf(fy, 0.f), 127.f);
    int y0 = (int)fy;
    float wy = fy - (float)y0;
    int y1 = min(y0 + 1, 127);
    const float* p = base + b * 128 * 128;
    const float* r0 = p + y0 * 128;
    const float* r1 = p + y1 * 128;
    float4 o;
    #pragma unroll
    for (int q = 0; q < 4; q++) {
        float fx = (j0 + q + 0.5f) * 0.25f - 0.5f;
        fx = fminf(fmaxf(fx, 0.f), 127.f);
        int x0 = (int)fx;
        float wx = fx - (float)x0;
        int x1 = min(x0 + 1, 127);
        float top = (1.f - wx) * r0[x0] + wx * r0[x1];
        float bot = (1.f - wx) * r1[x0] + wx * r1[x1];
        ((float*)&o)[q] = (1.f - wy) * top + wy * bot;
    }
    ((float4*)out)[idx] = o;
}

// ---------------- image warp (4 outputs/thread along x) ----------------
__global__ void k_warp4(const float* __restrict__ src, float* __restrict__ dst,
                        float* __restrict__ dst2, int thoff) {
    int idx = blockIdx.x * blockDim.x + threadIdx.x;
    if (idx >= BN * NPIX / 4) return;
    int b = idx / (NPIX / 4), r4 = idx - b * (NPIX / 4);
    int i = r4 >> 7;
    int j0 = (r4 & 127) * 4;
    const float* th = g_inv + (thoff + b) * 6;
    float t0 = th[0], t1 = th[1], t2 = th[2], t3 = th[3], t4 = th[4], t5 = th[5];
    float Y = (float)(2 * i + 1) / 512.0f - 1.0f;
    const float* s = src + b * NPIX;
    float4 o;
    #pragma unroll
    for (int q = 0; q < 4; q++) {
        float X = (float)(2 * (j0 + q) + 1) / 512.0f - 1.0f;
        float gx = t0 * X + t1 * Y + t2;
        float gy = t3 * X + t4 * Y + t5;
        ((float*)&o)[q] = bilin_sample(s, gx, gy, UPD, UPD);
    }
    ((float4*)dst)[idx] = o;
    if (dst2) ((float4*)dst2)[idx] = o;
}

// ---------------- mask stage 1: mask_j -> g_rm2 via g2 (4/thread) ----------------
__global__ void k_mask1(const float* __restrict__ masks) {
    int idx = blockIdx.x * blockDim.x + threadIdx.x;
    if (idx >= NM * BN * NPIX / 4) return;
    int jb = idx / (NPIX / 4), r4 = idx - jb * (NPIX / 4);
    int j = jb / BN, b = jb - j * BN;
    int i = r4 >> 7;
    int j0 = (r4 & 127) * 4;
    const float* th = g_inv + (1 * BN + b) * 6;
    float t0 = th[0], t1 = th[1], t2 = th[2], t3 = th[3], t4 = th[4], t5 = th[5];
    float Y = (float)(2 * i + 1) / 512.0f - 1.0f;
    const float* s = masks + j * NPIX;
    float4 o;
    #pragma unroll
    for (int q = 0; q < 4; q++) {
        float X = (float)(2 * (j0 + q) + 1) / 512.0f - 1.0f;
        float gx = t0 * X + t1 * Y + t2;
        float gy = t3 * X + t4 * Y + t5;
        ((float*)&o)[q] = bilin_sample(s, gx, gy, UPD, UPD);
    }
    ((float4*)g_rm2)[idx] = o;
}

// ---------------- mask stage 2 FUSED with COM pass 1 ----------------
// grid (64 chunks, NM*BN). Each block owns 4096 pixels of one (j,b) image:
// samples g_rm2 via g1, thresholds, writes masks_rot floats + packed bits,
// and block-reduces (sum img*m, sum m) -> g_part1. Deterministic tree order.
__global__ void k_mask2f(const float* __restrict__ img_all, float* __restrict__ out,
                         unsigned* __restrict__ bits) {
    int chunk = blockIdx.x, jb = blockIdx.y;
    int b = jb & (BN - 1);
    const float* th = g_inv + b * 6;   // inv(scaler_shear)
    float t0 = th[0], t1 = th[1], t2 = th[2], t3 = th[3], t4 = th[4], t5 = th[5];
    const float* src = g_rm2 + (size_t)jb * NPIX;
    const float* img = img_all + b * NPIX;
    int base = chunk * 4096;
    float sn = 0.f, sm = 0.f;
    for (int k = threadIdx.x; k < 4096; k += 512) {
        int g = base + k;
        int i = g >> 9, jj = g & 511;
        float X = (float)(2 * jj + 1) / 512.0f - 1.0f;
        float Y = (float)(2 * i + 1) / 512.0f - 1.0f;
        float gx = t0 * X + t1 * Y + t2;
        float gy = t3 * X + t4 * Y + t5;
        float v = bilin_sample(src, gx, gy, UPD, UPD);
        bool on = (v >= 0.5f);
        float mv = on ? 1.0f : 0.0f;
        out[(size_t)jb * NPIX + g] = mv;
        if (on) { sn += img[g]; sm += 1.0f; }
        unsigned w = __ballot_sync(0xffffffffu, on);
        if ((threadIdx.x & 31) == 0) bits[((size_t)jb * NPIX + g) >> 5] = w;
    }
    __shared__ float sh1[512], sh2[512];
    sh1[threadIdx.x] = sn; sh2[threadIdx.x] = sm;
    __syncthreads();
    for (int s = 256; s > 0; s >>= 1) {
        if (threadIdx.x < s) {
            sh1[threadIdx.x] += sh1[threadIdx.x + s];
            sh2[threadIdx.x] += sh2[threadIdx.x + s];
        }
        __syncthreads();
    }
    if (threadIdx.x == 0) {
        int o = (jb * 64 + chunk) * 2;
        g_part1[o] = sh1[0]; g_part1[o + 1] = sh2[0];
    }
}

__global__ void k_p2() {
    int t = threadIdx.x;
    if (t >= NM * BN) return;
    float sn = 0.f, sm = 0.f;
    for (int k = 0; k < 64; k++) {
        sn += g_part1[(t * 64 + k) * 2];
        sm += g_part1[(t * 64 + k) * 2 + 1];
    }
    float msum = fmaxf(sm, 1.0f);
    g_thr[t] = (sn / msum) * 1.5f;
}

// ---------------- COM pass 2 reading packed bits (8MB) + L2-resident image ----------------
__global__ void k_p3(const float* __restrict__ pin, const unsigned* __restrict__ bits) {
    int chunk = blockIdx.x, jb = blockIdx.y;
    int b = jb & (BN - 1);
    const float* img = pin + b * NPIX;
    float thr = g_thr[jb];
    int base = chunk * 4096;
    float st = 0.f, sx = 0.f, sy = 0.f;
    for (int k = threadIdx.x; k < 4096; k += 512) {
        int g = base + k;
        unsigned w = bits[((size_t)jb * NPIX + g) >> 5];
        if ((w >> (k & 31)) & 1u) {
            float nv = img[g];
            if (nv > thr) {
                st += nv;
                sx += nv * (float)(g >> 9);
                sy += nv * (float)(g & 511);
            }
        }
    }
    __shared__ float sh1[512], sh2[512], sh3[512];
    sh1[threadIdx.x] = st; sh2[threadIdx.x] = sx; sh3[threadIdx.x] = sy;
    __syncthreads();
    for (int s = 256; s > 0; s >>= 1) {
        if (threadIdx.x < s) {
            sh1[threadIdx.x] += sh1[threadIdx.x + s];
            sh2[threadIdx.x] += sh2[threadIdx.x + s];
            sh3[threadIdx.x] += sh3[threadIdx.x + s];
        }
        __syncthreads();
    }
    if (threadIdx.x == 0) {
        int o = (jb * 64 + chunk) * 3;
        g_part3[o] = sh1[0]; g_part3[o + 1] = sh2[0]; g_part3[o + 2] = sh3[0];
    }
}

// ---------------- revise (one block per batch item; sequential over j via launches) ----------------
__global__ void k_revise(float* __restrict__ rev, const float* __restrict__ adj, int j) {
    int b = blockIdx.x;
    int tid = threadIdx.x;
    __shared__ float red[64 * 3];
    __shared__ int sh_xy[2];
    if (tid < 64) {
        int o = ((j * BN + b) * 64 + tid) * 3;
        red[tid * 3 + 0] = g_part3[o];
        red[tid * 3 + 1] = g_part3[o + 1];
        red[tid * 3 + 2] = g_part3[o + 2];
    }
    __syncthreads();
    if (tid == 0) {
        float tot = 0.f, sx = 0.f, sy = 0.f;
        for (int k = 0; k < 64; k++) {
            tot += red[k * 3]; sx += red[k * 3 + 1]; sy += red[k * 3 + 2];
        }
        tot += 1e-8f;
        float cx = sx / tot, cy = sy / tot;
        int x0 = __float2int_rn(cx) - 60;            // round half to even
        int y0 = __float2int_rn(cy) - 60;
        x0 = min(max(x0, 0), UPD - PATCH);           // dynamic_slice clamping
        y0 = min(max(y0, 0), UPD - PATCH);
        sh_xy[0] = x0; sh_xy[1] = y0;
    }
    __syncthreads();
    int x0 = sh_xy[0], y0 = sh_xy[1];
    float a = adj[b];
    float* img = rev + b * NPIX;
    float* patch = g_patch + b * PATCH * PATCH;
    for (int t = tid; t < PATCH * PATCH; t += blockDim.x) {
        int p = t / PATCH, q = t - p * PATCH;
        float v = img[(x0 + p) * UPD + (y0 + q)];
        int dp = p - 60, dq = q - 60;
        if (dp * dp + dq * dq <= 16) v = v / a;
        patch[t] = v;
    }
    __syncthreads();
    const float* th = g_inv + b * 6;  // inv(scaler_shear)
    for (int t = tid; t < PATCH * PATCH; t += blockDim.x) {
        int p = t / PATCH, q = t - p * PATCH;
        float X = (float)(2 * q + 1) / 120.0f - 1.0f;
        float Y = (float)(2 * p + 1) / 120.0f - 1.0f;
        float gx = th[0] * X + th[1] * Y + th[2];
        float gy = th[3] * X + th[4] * Y + th[5];
        float v = bilin_sample(patch, gx, gy, PATCH, PATCH);
        img[(x0 + p) * UPD + (y0 + q)] = v;
    }
}

// ---------------- launch ----------------
extern "C" void kernel_launch(void* const* d_in, const int* in_sizes, int n_in,
                              void* d_out, int out_size) {
    const float* base  = (const float*)d_in[0];  // (16,1,128,128)
    const float* sc    = (const float*)d_in[1];  // (16,2,3)
    const float* ro    = (const float*)d_in[2];  // (16,2,3)
    const float* tr    = (const float*)d_in[3];  // (16,2,3)
    const float* adj   = (const float*)d_in[4];  // (16,)
    const float* masks = (const float*)d_in[5];  // (4,512,512)
    float* out = (float*)d_out;
    float* seg0 = out;                           // base_inp    (16,1,512,512)
    float* seg1 = out + (size_t)BN * NPIX;       // pred_input
    float* seg2 = out + (size_t)2 * BN * NPIX;   // pred_revise
    float* seg3 = out + (size_t)3 * BN * NPIX;   // masks_rot (4,16,512,512) 0/1

    unsigned* bits;
    cudaGetSymbolAddress((void**)&bits, g_bits);

    const int TB = 256;
    int nblk_img4 = (BN * NPIX / 4 + TB - 1) / TB;
    int nblk_msk4 = (NM * BN * NPIX / 4 + TB - 1) / TB;

    k_inv<<<1, 64>>>(sc, ro, tr);
    k_resize4<<<nblk_img4, TB>>>(base, seg0);
    k_warp4<<<nblk_img4, TB>>>(seg0, g_bufA, nullptr, 2 * BN);   // inv(translation)
    k_warp4<<<nblk_img4, TB>>>(g_bufA, g_bufB, nullptr, 1 * BN); // inv(rotation)
    k_warp4<<<nblk_img4, TB>>>(g_bufB, seg1, seg2, 0);           // inv(shear) -> pred_input & revise init
    k_mask1<<<nblk_msk4, TB>>>(masks);
    k_mask2f<<<dim3(64, NM * BN), 512>>>(seg1, seg3, bits);
    k_p2<<<1, 64>>>();
    k_p3<<<dim3(64, NM * BN), 512>>>(seg1, bits);
    for (int j = 0; j < NM; j++) {
        k_revise<<<BN, 512>>>(seg2, adj, j);
    }
}

// round 3
// speedup vs baseline: 2.4017x; 2.4017x over previous
#include <cuda_runtime.h>
#include <math.h>

#define BN 16
#define UPD 512
#define NPIX (UPD*UPD)
#define PATCH 120
#define NM 4

// ---------------- static device scratch (no runtime allocation) ----------------
__device__ float g_inv[3*BN*6];                 // inverse thetas: [which][b][6]
__device__ float g_bufA[BN*NPIX];               // pred_trans
__device__ float g_bufB[BN*NPIX];               // pred_rot
__device__ float g_rm2[NM*BN*NPIX];             // mask after g2 sample
__device__ unsigned g_bits[NM*BN*NPIX/32];      // packed masks_rot bits
__device__ float g_part1[NM*BN*64*2];           // partial sums (new, mask)
__device__ float g_part3[NM*BN*64*3];           // partial sums (tot, sx, sy)
__device__ float g_thr[NM*BN];                  // per (j,b) threshold
__device__ float g_patch[BN*PATCH*PATCH];       // revise patch snapshot

// ---------------- helpers ----------------
__device__ __forceinline__ float bilin_sample(const float* __restrict__ s,
                                              float gx, float gy, int H, int W) {
    // torch grid_sample: bilinear, zero padding, align_corners=False
    float x = ((gx + 1.0f) * (float)W - 1.0f) * 0.5f;
    float y = ((gy + 1.0f) * (float)H - 1.0f) * 0.5f;
    float xf = floorf(x), yf = floorf(y);
    int x0 = (int)xf, y0 = (int)yf;
    float wx = x - xf, wy = y - yf;
    int x1 = x0 + 1, y1 = y0 + 1;
    bool xi0 = (x0 >= 0) && (x0 < W);
    bool xi1 = (x1 >= 0) && (x1 < W);
    bool yi0 = (y0 >= 0) && (y0 < H);
    bool yi1 = (y1 >= 0) && (y1 < H);
    float v00 = 0.f, v01 = 0.f, v10 = 0.f, v11 = 0.f;
    if (yi0) {
        const float* row = s + y0 * W;
        if (xi0) v00 = __ldg(row + x0);
        if (xi1) v01 = __ldg(row + x1);
    }
    if (yi1) {
        const float* row = s + y1 * W;
        if (xi0) v10 = __ldg(row + x0);
        if (xi1) v11 = __ldg(row + x1);
    }
    return (1.f - wx) * (1.f - wy) * v00 + wx * (1.f - wy) * v01
         + (1.f - wx) * wy * v10 + wx * wy * v11;
}

// ---------------- K0: 2x3 affine inverses ----------------
__global__ void k_inv(const float* __restrict__ sc, const float* __restrict__ ro,
                      const float* __restrict__ tr) {
    int t = threadIdx.x;
    if (t >= 3 * BN) return;
    int w = t / BN, b = t % BN;
    const float* src = (w == 0) ? sc : ((w == 1) ? ro : tr);
    const float* m = src + b * 6;
    float a = m[0], bb = m[1], c = m[2], d = m[3], e = m[4], f = m[5];
    float det = a * e - bb * d;
    float ia = e / det, ib = -bb / det, id = -d / det, ie = a / det;
    float ic  = -(ia * c + ib * f);
    float iff = -(id * c + ie * f);
    float* o = g_inv + t * 6;
    o[0] = ia; o[1] = ib; o[2] = ic; o[3] = id; o[4] = ie; o[5] = iff;
}

// ---------------- K1: jax.image.resize linear, 4 outputs/thread ----------------
__global__ void k_resize4(const float* __restrict__ base, float* __restrict__ out) {
    int idx = blockIdx.x * blockDim.x + threadIdx.x;
    if (idx >= BN * NPIX / 4) return;
    int b = idx / (NPIX / 4), r4 = idx - b * (NPIX / 4);
    int i = r4 >> 7;
    int j0 = (r4 & 127) * 4;
    float fy = (i + 0.5f) * 0.25f - 0.5f;
    fy = fminf(fmaxf(fy, 0.f), 127.f);
    int y0 = (int)fy;
    float wy = fy - (float)y0;
    int y1 = min(y0 + 1, 127);
    const float* p = base + b * 128 * 128;
    const float* r0 = p + y0 * 128;
    const float* r1 = p + y1 * 128;
    float4 o;
    #pragma unroll
    for (int q = 0; q < 4; q++) {
        float fx = (j0 + q + 0.5f) * 0.25f - 0.5f;
        fx = fminf(fmaxf(fx, 0.f), 127.f);
        int x0 = (int)fx;
        float wx = fx - (float)x0;
        int x1 = min(x0 + 1, 127);
        float top = (1.f - wx) * __ldg(r0 + x0) + wx * __ldg(r0 + x1);
        float bot = (1.f - wx) * __ldg(r1 + x0) + wx * __ldg(r1 + x1);
        ((float*)&o)[q] = (1.f - wy) * top + wy * bot;
    }
    ((float4*)out)[idx] = o;
}

// ---------------- image warp (4 outputs/thread along x) ----------------
__global__ void k_warp4(const float* __restrict__ src, float* __restrict__ dst,
                        float* __restrict__ dst2, int thoff) {
    int idx = blockIdx.x * blockDim.x + threadIdx.x;
    if (idx >= BN * NPIX / 4) return;
    int b = idx / (NPIX / 4), r4 = idx - b * (NPIX / 4);
    int i = r4 >> 7;
    int j0 = (r4 & 127) * 4;
    const float* th = g_inv + (thoff + b) * 6;
    float t0 = th[0], t1 = th[1], t2 = th[2], t3 = th[3], t4 = th[4], t5 = th[5];
    float Y = (float)(2 * i + 1) / 512.0f - 1.0f;
    const float* s = src + b * NPIX;
    float4 o;
    #pragma unroll
    for (int q = 0; q < 4; q++) {
        float X = (float)(2 * (j0 + q) + 1) / 512.0f - 1.0f;
        float gx = t0 * X + t1 * Y + t2;
        float gy = t3 * X + t4 * Y + t5;
        ((float*)&o)[q] = bilin_sample(s, gx, gy, UPD, UPD);
    }
    ((float4*)dst)[idx] = o;
    if (dst2) ((float4*)dst2)[idx] = o;
}

// ---------------- mask stage 1: mask_j -> g_rm2 via g2 (4/thread) ----------------
__global__ void k_mask1(const float* __restrict__ masks) {
    int idx = blockIdx.x * blockDim.x + threadIdx.x;
    if (idx >= NM * BN * NPIX / 4) return;
    int jb = idx / (NPIX / 4), r4 = idx - jb * (NPIX / 4);
    int j = jb / BN, b = jb - j * BN;
    int i = r4 >> 7;
    int j0 = (r4 & 127) * 4;
    const float* th = g_inv + (1 * BN + b) * 6;
    float t0 = th[0], t1 = th[1], t2 = th[2], t3 = th[3], t4 = th[4], t5 = th[5];
    float Y = (float)(2 * i + 1) / 512.0f - 1.0f;
    const float* s = masks + j * NPIX;
    float4 o;
    #pragma unroll
    for (int q = 0; q < 4; q++) {
        float X = (float)(2 * (j0 + q) + 1) / 512.0f - 1.0f;
        float gx = t0 * X + t1 * Y + t2;
        float gy = t3 * X + t4 * Y + t5;
        ((float*)&o)[q] = bilin_sample(s, gx, gy, UPD, UPD);
    }
    ((float4*)g_rm2)[idx] = o;
}

// ---------------- mask stage 2 FUSED with COM pass 1 ----------------
// grid (64 chunks, NM*BN). Each block owns 4096 pixels of one (j,b) image:
// samples g_rm2 via g1, thresholds, writes masks_rot floats + packed bits,
// and block-reduces (sum img*m, sum m) -> g_part1. Deterministic tree order.
__global__ void k_mask2f(const float* __restrict__ img_all, float* __restrict__ out,
                         unsigned* __restrict__ bits) {
    int chunk = blockIdx.x, jb = blockIdx.y;
    int b = jb & (BN - 1);
    const float* th = g_inv + b * 6;   // inv(scaler_shear)
    float t0 = th[0], t1 = th[1], t2 = th[2], t3 = th[3], t4 = th[4], t5 = th[5];
    const float* src = g_rm2 + (size_t)jb * NPIX;
    const float* img = img_all + b * NPIX;
    int base = chunk * 4096;
    float sn = 0.f, sm = 0.f;
    for (int k = threadIdx.x; k < 4096; k += 512) {
        int g = base + k;
        int i = g >> 9, jj = g & 511;
        float X = (float)(2 * jj + 1) / 512.0f - 1.0f;
        float Y = (float)(2 * i + 1) / 512.0f - 1.0f;
        float gx = t0 * X + t1 * Y + t2;
        float gy = t3 * X + t4 * Y + t5;
        float v = bilin_sample(src, gx, gy, UPD, UPD);
        bool on = (v >= 0.5f);
        float mv = on ? 1.0f : 0.0f;
        out[(size_t)jb * NPIX + g] = mv;
        if (on) { sn += img[g]; sm += 1.0f; }
        unsigned w = __ballot_sync(0xffffffffu, on);
        if ((threadIdx.x & 31) == 0) bits[((size_t)jb * NPIX + g) >> 5] = w;
    }
    __shared__ float sh1[512], sh2[512];
    sh1[threadIdx.x] = sn; sh2[threadIdx.x] = sm;
    __syncthreads();
    for (int s = 256; s > 0; s >>= 1) {
        if (threadIdx.x < s) {
            sh1[threadIdx.x] += sh1[threadIdx.x + s];
            sh2[threadIdx.x] += sh2[threadIdx.x + s];
        }
        __syncthreads();
    }
    if (threadIdx.x == 0) {
        int o = (jb * 64 + chunk) * 2;
        g_part1[o] = sh1[0]; g_part1[o + 1] = sh2[0];
    }
}

__global__ void k_p2() {
    int t = threadIdx.x;
    if (t >= NM * BN) return;
    float sn = 0.f, sm = 0.f;
    for (int k = 0; k < 64; k++) {
        sn += g_part1[(t * 64 + k) * 2];
        sm += g_part1[(t * 64 + k) * 2 + 1];
    }
    float msum = fmaxf(sm, 1.0f);
    g_thr[t] = (sn / msum) * 1.5f;
}

// ---------------- COM pass 2 reading packed bits (8MB) + L2-resident image ----------------
__global__ void k_p3(const float* __restrict__ pin, const unsigned* __restrict__ bits) {
    int chunk = blockIdx.x, jb = blockIdx.y;
    int b = jb & (BN - 1);
    const float* img = pin + b * NPIX;
    float thr = g_thr[jb];
    int base = chunk * 4096;
    float st = 0.f, sx = 0.f, sy = 0.f;
    for (int k = threadIdx.x; k < 4096; k += 512) {
        int g = base + k;
        unsigned w = bits[((size_t)jb * NPIX + g) >> 5];
        if ((w >> (k & 31)) & 1u) {
            float nv = img[g];
            if (nv > thr) {
                st += nv;
                sx += nv * (float)(g >> 9);
                sy += nv * (float)(g & 511);
            }
        }
    }
    __shared__ float sh1[512], sh2[512], sh3[512];
    sh1[threadIdx.x] = st; sh2[threadIdx.x] = sx; sh3[threadIdx.x] = sy;
    __syncthreads();
    for (int s = 256; s > 0; s >>= 1) {
        if (threadIdx.x < s) {
            sh1[threadIdx.x] += sh1[threadIdx.x + s];
            sh2[threadIdx.x] += sh2[threadIdx.x + s];
            sh3[threadIdx.x] += sh3[threadIdx.x + s];
        }
        __syncthreads();
    }
    if (threadIdx.x == 0) {
        int o = (jb * 64 + chunk) * 3;
        g_part3[o] = sh1[0]; g_part3[o + 1] = sh2[0]; g_part3[o + 2] = sh3[0];
    }
}

// ---------------- revise (one block per batch item; sequential over j via launches) ----------------
__global__ void k_revise(float* __restrict__ rev, const float* __restrict__ adj, int j) {
    int b = blockIdx.x;
    int tid = threadIdx.x;
    __shared__ float red[64 * 3];
    __shared__ int sh_xy[2];
    if (tid < 64) {
        int o = ((j * BN + b) * 64 + tid) * 3;
        red[tid * 3 + 0] = g_part3[o];
        red[tid * 3 + 1] = g_part3[o + 1];
        red[tid * 3 + 2] = g_part3[o + 2];
    }
    __syncthreads();
    if (tid == 0) {
        float tot = 0.f, sx = 0.f, sy = 0.f;
        for (int k = 0; k < 64; k++) {
            tot += red[k * 3]; sx += red[k * 3 + 1]; sy += red[k * 3 + 2];
        }
        tot += 1e-8f;
        float cx = sx / tot, cy = sy / tot;
        int x0 = __float2int_rn(cx) - 60;            // round half to even
        int y0 = __float2int_rn(cy) - 60;
        x0 = min(max(x0, 0), UPD - PATCH);           // dynamic_slice clamping
        y0 = min(max(y0, 0), UPD - PATCH);
        sh_xy[0] = x0; sh_xy[1] = y0;
    }
    __syncthreads();
    int x0 = sh_xy[0], y0 = sh_xy[1];
    float a = adj[b];
    float* img = rev + b * NPIX;
    float* patch = g_patch + b * PATCH * PATCH;
    for (int t = tid; t < PATCH * PATCH; t += blockDim.x) {
        int p = t / PATCH, q = t - p * PATCH;
        float v = img[(x0 + p) * UPD + (y0 + q)];
        int dp = p - 60, dq = q - 60;
        if (dp * dp + dq * dq <= 16) v = v / a;
        patch[t] = v;
    }
    __syncthreads();
    const float* th = g_inv + b * 6;  // inv(scaler_shear)
    for (int t = tid; t < PATCH * PATCH; t += blockDim.x) {
        int p = t / PATCH, q = t - p * PATCH;
        float X = (float)(2 * q + 1) / 120.0f - 1.0f;
        float Y = (float)(2 * p + 1) / 120.0f - 1.0f;
        float gx = th[0] * X + th[1] * Y + th[2];
        float gy = th[3] * X + th[4] * Y + th[5];
        float v = bilin_sample(patch, gx, gy, PATCH, PATCH);
        img[(x0 + p) * UPD + (y0 + q)] = v;
    }
}

// ---------------- launch ----------------
extern "C" void kernel_launch(void* const* d_in, const int* in_sizes, int n_in,
                              void* d_out, int out_size) {
    const float* base  = (const float*)d_in[0];  // (16,1,128,128)
    const float* sc    = (const float*)d_in[1];  // (16,2,3)
    const float* ro    = (const float*)d_in[2];  // (16,2,3)
    const float* tr    = (const float*)d_in[3];  // (16,2,3)
    const float* adj   = (const float*)d_in[4];  // (16,)
    const float* masks = (const float*)d_in[5];  // (4,512,512)
    float* out = (float*)d_out;
    float* seg0 = out;                           // base_inp    (16,1,512,512)
    float* seg1 = out + (size_t)BN * NPIX;       // pred_input
    float* seg2 = out + (size_t)2 * BN * NPIX;   // pred_revise
    float* seg3 = out + (size_t)3 * BN * NPIX;   // masks_rot (4,16,512,512) 0/1

    // DEVICE addresses of __device__ scratch (host-side symbol addresses route
    // over NVLink-C2C to host DRAM on GB300 — the round-2 regression).
    float *bufA, *bufB;
    unsigned* bits;
    cudaGetSymbolAddress((void**)&bufA, g_bufA);
    cudaGetSymbolAddress((void**)&bufB, g_bufB);
    cudaGetSymbolAddress((void**)&bits, g_bits);

    const int TB = 256;
    int nblk_img4 = (BN * NPIX / 4 + TB - 1) / TB;
    int nblk_msk4 = (NM * BN * NPIX / 4 + TB - 1) / TB;

    k_inv<<<1, 64>>>(sc, ro, tr);
    k_resize4<<<nblk_img4, TB>>>(base, seg0);
    k_warp4<<<nblk_img4, TB>>>(seg0, bufA, nullptr, 2 * BN);   // inv(translation)
    k_warp4<<<nblk_img4, TB>>>(bufA, bufB, nullptr, 1 * BN);   // inv(rotation)
    k_warp4<<<nblk_img4, TB>>>(bufB, seg1, seg2, 0);           // inv(shear) -> pred_input & revise init
    k_mask1<<<nblk_msk4, TB>>>(masks);
    k_mask2f<<<dim3(64, NM * BN), 512>>>(seg1, seg3, bits);
    k_p2<<<1, 64>>>();
    k_p3<<<dim3(64, NM * BN), 512>>>(seg1, bits);
    for (int j = 0; j < NM; j++) {
        k_revise<<<BN, 512>>>(seg2, adj, j);
    }
}

// round 4
// speedup vs baseline: 4.1643x; 1.7339x over previous
#include <cuda_runtime.h>
#include <math.h>

#define BN 16
#define UPD 512
#define NPIX (UPD*UPD)
#define PATCH 120
#define NM 4
#define KB 16          // blocks per (j,b) for box-restricted kernels
#define TPB 256

// ---------------- static device scratch (zero-initialized at load) ----------------
__device__ float g_inv[3*BN*6];                 // inverse thetas: [which][b][6]
__device__ float g_bufA[BN*NPIX];               // pred_trans
__device__ float g_bufB[BN*NPIX];               // pred_rot
__device__ float g_rm2[NM*BN*NPIX];             // mask after g2 sample (zero outside boxes)
__device__ int4  g_srcpart[NM*8];               // per-j partial src bboxes
__device__ int4  g_box1[NM*BN];                 // stage-1 write box (r0,c0,h,w)
__device__ int4  g_box2[NM*BN];                 // stage-2 box (r0,c0,h,w)
__device__ float g_part1[NM*BN*KB*2];           // partial sums (new, mask)
__device__ float g_part3[NM*BN*KB*3];           // partial sums (tot, sx, sy)
__device__ float g_thr[NM*BN];                  // per (j,b) threshold
__device__ float g_patch[BN*PATCH*PATCH];       // revise patch snapshot

// ---------------- helpers ----------------
__device__ __forceinline__ float bilin_sample(const float* __restrict__ s,
                                              float gx, float gy, int H, int W) {
    // torch grid_sample: bilinear, zero padding, align_corners=False
    float x = ((gx + 1.0f) * (float)W - 1.0f) * 0.5f;
    float y = ((gy + 1.0f) * (float)H - 1.0f) * 0.5f;
    float xf = floorf(x), yf = floorf(y);
    int x0 = (int)xf, y0 = (int)yf;
    float wx = x - xf, wy = y - yf;
    int x1 = x0 + 1, y1 = y0 + 1;
    bool xi0 = (x0 >= 0) && (x0 < W);
    bool xi1 = (x1 >= 0) && (x1 < W);
    bool yi0 = (y0 >= 0) && (y0 < H);
    bool yi1 = (y1 >= 0) && (y1 < H);
    float v00 = 0.f, v01 = 0.f, v10 = 0.f, v11 = 0.f;
    if (yi0) {
        const float* row = s + y0 * W;
        if (xi0) v00 = __ldg(row + x0);
        if (xi1) v01 = __ldg(row + x1);
    }
    if (yi1) {
        const float* row = s + y1 * W;
        if (xi0) v10 = __ldg(row + x0);
        if (xi1) v11 = __ldg(row + x1);
    }
    return (1.f - wx) * (1.f - wy) * v00 + wx * (1.f - wy) * v01
         + (1.f - wx) * wy * v10 + wx * wy * v11;
}

// ---------------- K0: 2x3 affine inverses ----------------
__global__ void k_inv(const float* __restrict__ sc, const float* __restrict__ ro,
                      const float* __restrict__ tr) {
    int t = threadIdx.x;
    if (t >= 3 * BN) return;
    int w = t / BN, b = t % BN;
    const float* src = (w == 0) ? sc : ((w == 1) ? ro : tr);
    const float* m = src + b * 6;
    float a = m[0], bb = m[1], c = m[2], d = m[3], e = m[4], f = m[5];
    float det = a * e - bb * d;
    float ia = e / det, ib = -bb / det, id = -d / det, ie = a / det;
    float ic  = -(ia * c + ib * f);
    float iff = -(id * c + ie * f);
    float* o = g_inv + t * 6;
    o[0] = ia; o[1] = ib; o[2] = ic; o[3] = id; o[4] = ie; o[5] = iff;
}

// ---------------- source mask bbox (partials) ----------------
__global__ void k_srcbox(const float* __restrict__ masks) {
    int j = blockIdx.y, seg = blockIdx.x;       // 8 segments per mask plane
    const float* m = masks + j * NPIX;
    int base = seg * (NPIX / 8);
    int rmin = 1 << 20, rmax = -1, cmin = 1 << 20, cmax = -1;
    for (int k = threadIdx.x; k < NPIX / 8; k += TPB) {
        int g = base + k;
        if (m[g] != 0.0f) {
            int r = g >> 9, c = g & 511;
            rmin = min(rmin, r); rmax = max(rmax, r);
            cmin = min(cmin, c); cmax = max(cmax, c);
        }
    }
    __shared__ int s0[TPB], s1[TPB], s2[TPB], s3[TPB];
    s0[threadIdx.x] = rmin; s1[threadIdx.x] = rmax;
    s2[threadIdx.x] = cmin; s3[threadIdx.x] = cmax;
    __syncthreads();
    for (int s = TPB / 2; s > 0; s >>= 1) {
        if (threadIdx.x < s) {
            s0[threadIdx.x] = min(s0[threadIdx.x], s0[threadIdx.x + s]);
            s1[threadIdx.x] = max(s1[threadIdx.x], s1[threadIdx.x + s]);
            s2[threadIdx.x] = min(s2[threadIdx.x], s2[threadIdx.x + s]);
            s3[threadIdx.x] = max(s3[threadIdx.x], s3[threadIdx.x + s]);
        }
        __syncthreads();
    }
    if (threadIdx.x == 0)
        g_srcpart[j * 8 + seg] = make_int4(s0[0], s1[0], s2[0], s3[0]);
}

// ---------------- per-(j,b) output boxes via affine preimages ----------------
__device__ __forceinline__ void preimage_px(const float* th,
        float ya, float yb, float xa, float xb,
        int& ir0, int& ir1, int& ic0, int& ic1) {
    // rect in source pixel coords (y=row in [ya,yb], x=col in [xa,xb]) ->
    // bbox of pixels whose sample point can land in it, +1 dilation.
    float gxa = (2.f * xa + 1.f) / 512.f - 1.f, gxb = (2.f * xb + 1.f) / 512.f - 1.f;
    float gya = (2.f * ya + 1.f) / 512.f - 1.f, gyb = (2.f * yb + 1.f) / 512.f - 1.f;
    float det = th[0] * th[4] - th[1] * th[3];
    float Xmin = 1e30f, Xmax = -1e30f, Ymin = 1e30f, Ymax = -1e30f;
    #pragma unroll
    for (int u = 0; u < 4; u++) {
        float gx = (u & 1) ? gxb : gxa;
        float gy = (u & 2) ? gyb : gya;
        float rx = gx - th[2], ry = gy - th[5];
        float X = ( th[4] * rx - th[1] * ry) / det;
        float Y = (-th[3] * rx + th[0] * ry) / det;
        Xmin = fminf(Xmin, X); Xmax = fmaxf(Xmax, X);
        Ymin = fminf(Ymin, Y); Ymax = fmaxf(Ymax, Y);
    }
    float jmin = ((Xmin + 1.f) * 512.f - 1.f) * 0.5f;
    float jmax = ((Xmax + 1.f) * 512.f - 1.f) * 0.5f;
    float imin = ((Ymin + 1.f) * 512.f - 1.f) * 0.5f;
    float imax = ((Ymax + 1.f) * 512.f - 1.f) * 0.5f;
    ir0 = max(0,   (int)floorf(imin) - 1);
    ir1 = min(511, (int)ceilf(imax) + 1);
    ic0 = max(0,   (int)floorf(jmin) - 1);
    ic1 = min(511, (int)ceilf(jmax) + 1);
}

__global__ void k_boxes() {
    int t = threadIdx.x;
    if (t >= NM * BN) return;
    int j = t / BN, b = t % BN;
    // combine src partials
    int r0 = 1 << 20, r1 = -1, c0 = 1 << 20, c1 = -1;
    for (int k = 0; k < 8; k++) {
        int4 p = g_srcpart[j * 8 + k];
        r0 = min(r0, p.x); r1 = max(r1, p.y);
        c0 = min(c0, p.z); c1 = max(c1, p.w);
    }
    if (r1 < r0) {  // empty mask
        g_box1[t] = make_int4(0, 0, 0, 0);
        g_box2[t] = make_int4(0, 0, 0, 0);
        return;
    }
    // stage 1: sampled via g2 = inv(rotation)
    int a0, a1, b0, b1;
    preimage_px(g_inv + (BN + b) * 6,
                (float)r0 - 1.f, (float)r1 + 1.f,
                (float)c0 - 1.f, (float)c1 + 1.f, a0, a1, b0, b1);
    // write box = core dilated by 2 (covers stage-2 tap footprint)
    int w0 = max(0, a0 - 2), w1 = min(511, a1 + 2);
    int w2 = max(0, b0 - 2), w3 = min(511, b1 + 2);
    g_box1[t] = make_int4(w0, w2, w1 - w0 + 1, w3 - w2 + 1);
    // stage 2: sampled via g1 = inv(shear); target rect = stage-1 core box
    int d0, d1, e0, e1;
    preimage_px(g_inv + b * 6,
                (float)a0 - 1.f, (float)a1 + 1.f,
                (float)b0 - 1.f, (float)b1 + 1.f, d0, d1, e0, e1);
    d0 = max(0, d0 - 1); d1 = min(511, d1 + 1);
    e0 = max(0, e0 - 1); e1 = min(511, e1 + 1);
    g_box2[t] = make_int4(d0, e0, d1 - d0 + 1, e1 - e0 + 1);
}

// ---------------- zero-fill (float4) ----------------
__global__ void k_zero4(float4* __restrict__ p, int n4) {
    int idx = blockIdx.x * blockDim.x + threadIdx.x;
    float4 z = make_float4(0.f, 0.f, 0.f, 0.f);
    for (int k = idx; k < n4; k += gridDim.x * blockDim.x) p[k] = z;
}

// ---------------- K1: jax.image.resize linear, 4 outputs/thread ----------------
__global__ void k_resize4(const float* __restrict__ base, float* __restrict__ out) {
    int idx = blockIdx.x * blockDim.x + threadIdx.x;
    if (idx >= BN * NPIX / 4) return;
    int b = idx / (NPIX / 4), r4 = idx - b * (NPIX / 4);
    int i = r4 >> 7;
    int j0 = (r4 & 127) * 4;
    float fy = (i + 0.5f) * 0.25f - 0.5f;
    fy = fminf(fmaxf(fy, 0.f), 127.f);
    int y0 = (int)fy;
    float wy = fy - (float)y0;
    int y1 = min(y0 + 1, 127);
    const float* p = base + b * 128 * 128;
    const float* r0 = p + y0 * 128;
    const float* r1 = p + y1 * 128;
    float4 o;
    #pragma unroll
    for (int q = 0; q < 4; q++) {
        float fx = (j0 + q + 0.5f) * 0.25f - 0.5f;
        fx = fminf(fmaxf(fx, 0.f), 127.f);
        int x0 = (int)fx;
        float wx = fx - (float)x0;
        int x1 = min(x0 + 1, 127);
        float top = (1.f - wx) * __ldg(r0 + x0) + wx * __ldg(r0 + x1);
        float bot = (1.f - wx) * __ldg(r1 + x0) + wx * __ldg(r1 + x1);
        ((float*)&o)[q] = (1.f - wy) * top + wy * bot;
    }
    ((float4*)out)[idx] = o;
}

// ---------------- image warp (4 outputs/thread along x) ----------------
__global__ void k_warp4(const float* __restrict__ src, float* __restrict__ dst,
                        float* __restrict__ dst2, int thoff) {
    int idx = blockIdx.x * blockDim.x + threadIdx.x;
    if (idx >= BN * NPIX / 4) return;
    int b = idx / (NPIX / 4), r4 = idx - b * (NPIX / 4);
    int i = r4 >> 7;
    int j0 = (r4 & 127) * 4;
    const float* th = g_inv + (thoff + b) * 6;
    float t0 = th[0], t1 = th[1], t2 = th[2], t3 = th[3], t4 = th[4], t5 = th[5];
    float Y = (float)(2 * i + 1) / 512.0f - 1.0f;
    const float* s = src + b * NPIX;
    float4 o;
    #pragma unroll
    for (int q = 0; q < 4; q++) {
        float X = (float)(2 * (j0 + q) + 1) / 512.0f - 1.0f;
        float gx = t0 * X + t1 * Y + t2;
        float gy = t3 * X + t4 * Y + t5;
        ((float*)&o)[q] = bilin_sample(s, gx, gy, UPD, UPD);
    }
    ((float4*)dst)[idx] = o;
    if (dst2) ((float4*)dst2)[idx] = o;
}

// ---------------- mask stage 1 (box-restricted): mask_j -> g_rm2 via g2 ----------------
__global__ void k_mask1(const float* __restrict__ masks) {
    int jb = blockIdx.y;
    int j = jb / BN, b = jb % BN;
    int4 bx = g_box1[jb];
    int area = bx.z * bx.w;
    const float* th = g_inv + (BN + b) * 6;
    float t0 = th[0], t1 = th[1], t2 = th[2], t3 = th[3], t4 = th[4], t5 = th[5];
    const float* s = masks + j * NPIX;
    float* dst = g_rm2 + (size_t)jb * NPIX;
    for (int t = blockIdx.x * TPB + threadIdx.x; t < area; t += KB * TPB) {
        int i = bx.x + t / bx.w, jj = bx.y + t % bx.w;
        float X = (float)(2 * jj + 1) / 512.0f - 1.0f;
        float Y = (float)(2 * i + 1) / 512.0f - 1.0f;
        float gx = t0 * X + t1 * Y + t2;
        float gy = t3 * X + t4 * Y + t5;
        dst[(i << 9) + jj] = bilin_sample(s, gx, gy, UPD, UPD);
    }
}

// ---------------- mask stage 2 (box-restricted) FUSED with COM pass 1 ----------------
__global__ void k_mask2f(const float* __restrict__ img_all, float* __restrict__ out) {
    int jb = blockIdx.y;
    int b = jb % BN;
    int4 bx = g_box2[jb];
    int area = bx.z * bx.w;
    const float* th = g_inv + b * 6;   // inv(scaler_shear)
    float t0 = th[0], t1 = th[1], t2 = th[2], t3 = th[3], t4 = th[4], t5 = th[5];
    const float* src = g_rm2 + (size_t)jb * NPIX;
    const float* img = img_all + b * NPIX;
    float* dst = out + (size_t)jb * NPIX;
    float sn = 0.f, sm = 0.f;
    for (int t = blockIdx.x * TPB + threadIdx.x; t < area; t += KB * TPB) {
        int i = bx.x + t / bx.w, jj = bx.y + t % bx.w;
        float X = (float)(2 * jj + 1) / 512.0f - 1.0f;
        float Y = (float)(2 * i + 1) / 512.0f - 1.0f;
        float gx = t0 * X + t1 * Y + t2;
        float gy = t3 * X + t4 * Y + t5;
        float v = bilin_sample(src, gx, gy, UPD, UPD);
        int g = (i << 9) + jj;
        bool on = (v >= 0.5f);
        dst[g] = on ? 1.0f : 0.0f;
        if (on) { sn += img[g]; sm += 1.0f; }
    }
    __shared__ float sh1[TPB], sh2[TPB];
    sh1[threadIdx.x] = sn; sh2[threadIdx.x] = sm;
    __syncthreads();
    for (int s = TPB / 2; s > 0; s >>= 1) {
        if (threadIdx.x < s) {
            sh1[threadIdx.x] += sh1[threadIdx.x + s];
            sh2[threadIdx.x] += sh2[threadIdx.x + s];
        }
        __syncthreads();
    }
    if (threadIdx.x == 0) {
        int o = (jb * KB + blockIdx.x) * 2;
        g_part1[o] = sh1[0]; g_part1[o + 1] = sh2[0];
    }
}

__global__ void k_p2() {
    int t = threadIdx.x;
    if (t >= NM * BN) return;
    float sn = 0.f, sm = 0.f;
    for (int k = 0; k < KB; k++) {
        sn += g_part1[(t * KB + k) * 2];
        sm += g_part1[(t * KB + k) * 2 + 1];
    }
    float msum = fmaxf(sm, 1.0f);
    g_thr[t] = (sn / msum) * 1.5f;
}

// ---------------- COM pass 2 (box-restricted) ----------------
__global__ void k_p3(const float* __restrict__ pin, const float* __restrict__ mrot) {
    int jb = blockIdx.y;
    int b = jb % BN;
    int4 bx = g_box2[jb];
    int area = bx.z * bx.w;
    const float* img = pin + b * NPIX;
    const float* m = mrot + (size_t)jb * NPIX;
    float thr = g_thr[jb];
    float st = 0.f, sx = 0.f, sy = 0.f;
    for (int t = blockIdx.x * TPB + threadIdx.x; t < area; t += KB * TPB) {
        int i = bx.x + t / bx.w, jj = bx.y + t % bx.w;
        int g = (i << 9) + jj;
        if (m[g] > 0.5f) {
            float nv = img[g];
            if (nv > thr) {
                st += nv;
                sx += nv * (float)i;
                sy += nv * (float)jj;
            }
        }
    }
    __shared__ float sh1[TPB], sh2[TPB], sh3[TPB];
    sh1[threadIdx.x] = st; sh2[threadIdx.x] = sx; sh3[threadIdx.x] = sy;
    __syncthreads();
    for (int s = TPB / 2; s > 0; s >>= 1) {
        if (threadIdx.x < s) {
            sh1[threadIdx.x] += sh1[threadIdx.x + s];
            sh2[threadIdx.x] += sh2[threadIdx.x + s];
            sh3[threadIdx.x] += sh3[threadIdx.x + s];
        }
        __syncthreads();
    }
    if (threadIdx.x == 0) {
        int o = (jb * KB + blockIdx.x) * 3;
        g_part3[o] = sh1[0]; g_part3[o + 1] = sh2[0]; g_part3[o + 2] = sh3[0];
    }
}

// ---------------- revise: one block per batch item, internal loop over j ----------------
__global__ void k_revise(float* __restrict__ rev, const float* __restrict__ adj) {
    int b = blockIdx.x;
    int tid = threadIdx.x;
    float a = adj[b];
    float* img = rev + b * NPIX;
    float* patch = g_patch + b * PATCH * PATCH;
    const float* th = g_inv + b * 6;  // inv(scaler_shear)
    __shared__ int sh_xy[2];
    for (int j = 0; j < NM; j++) {
        if (tid == 0) {
            float tot = 0.f, sx = 0.f, sy = 0.f;
            for (int k = 0; k < KB; k++) {
                int o = ((j * BN + b) * KB + k) * 3;
                tot += g_part3[o]; sx += g_part3[o + 1]; sy += g_part3[o + 2];
            }
            tot += 1e-8f;
            float cx = sx / tot, cy = sy / tot;
            int x0 = __float2int_rn(cx) - 60;            // round half to even
            int y0 = __float2int_rn(cy) - 60;
            x0 = min(max(x0, 0), UPD - PATCH);           // dynamic_slice clamping
            y0 = min(max(y0, 0), UPD - PATCH);
            sh_xy[0] = x0; sh_xy[1] = y0;
        }
        __syncthreads();
        int x0 = sh_xy[0], y0 = sh_xy[1];
        for (int t = tid; t < PATCH * PATCH; t += blockDim.x) {
            int p = t / PATCH, q = t - p * PATCH;
            float v = img[(x0 + p) * UPD + (y0 + q)];
            int dp = p - 60, dq = q - 60;
            if (dp * dp + dq * dq <= 16) v = v / a;
            patch[t] = v;
        }
        __syncthreads();
        for (int t = tid; t < PATCH * PATCH; t += blockDim.x) {
            int p = t / PATCH, q = t - p * PATCH;
            float X = (float)(2 * q + 1) / 120.0f - 1.0f;
            float Y = (float)(2 * p + 1) / 120.0f - 1.0f;
            float gx = th[0] * X + th[1] * Y + th[2];
            float gy = th[3] * X + th[4] * Y + th[5];
            float v = bilin_sample(patch, gx, gy, PATCH, PATCH);
            img[(x0 + p) * UPD + (y0 + q)] = v;
        }
        __syncthreads();
    }
}

// ---------------- launch ----------------
extern "C" void kernel_launch(void* const* d_in, const int* in_sizes, int n_in,
                              void* d_out, int out_size) {
    const float* base  = (const float*)d_in[0];  // (16,1,128,128)
    const float* sc    = (const float*)d_in[1];  // (16,2,3)
    const float* ro    = (const float*)d_in[2];  // (16,2,3)
    const float* tr    = (const float*)d_in[3];  // (16,2,3)
    const float* adj   = (const float*)d_in[4];  // (16,)
    const float* masks = (const float*)d_in[5];  // (4,512,512)
    float* out = (float*)d_out;
    float* seg0 = out;                           // base_inp    (16,1,512,512)
    float* seg1 = out + (size_t)BN * NPIX;       // pred_input
    float* seg2 = out + (size_t)2 * BN * NPIX;   // pred_revise
    float* seg3 = out + (size_t)3 * BN * NPIX;   // masks_rot (4,16,512,512) 0/1

    // DEVICE addresses of __device__ scratch (host-side symbol addresses route
    // over NVLink-C2C to host DRAM on GB300 — the round-2 regression).
    float *bufA, *bufB;
    cudaGetSymbolAddress((void**)&bufA, g_bufA);
    cudaGetSymbolAddress((void**)&bufB, g_bufB);

    int nblk_img4 = (BN * NPIX / 4 + TPB - 1) / TPB;

    k_inv<<<1, 64>>>(sc, ro, tr);
    k_srcbox<<<dim3(8, NM), TPB>>>(masks);
    k_boxes<<<1, 64>>>();
    k_zero4<<<4096, TPB>>>((float4*)seg3, NM * BN * NPIX / 4);
    k_resize4<<<nblk_img4, TPB>>>(base, seg0);
    k_warp4<<<nblk_img4, TPB>>>(seg0, bufA, nullptr, 2 * BN);   // inv(translation)
    k_warp4<<<nblk_img4, TPB>>>(bufA, bufB, nullptr, 1 * BN);   // inv(rotation)
    k_warp4<<<nblk_img4, TPB>>>(bufB, seg1, seg2, 0);           // inv(shear)
    k_mask1<<<dim3(KB, NM * BN), TPB>>>(masks);
    k_mask2f<<<dim3(KB, NM * BN), TPB>>>(seg1, seg3);
    k_p2<<<1, 64>>>();
    k_p3<<<dim3(KB, NM * BN), TPB>>>(seg1, seg3);
    k_revise<<<BN, 512>>>(seg2, adj);
}

// round 5
// speedup vs baseline: 4.2317x; 1.0162x over previous
#include <cuda_runtime.h>
#include <math.h>

#define BN 16
#define UPD 512
#define NPIX (UPD*UPD)
#define PATCH 120
#define NM 4
#define KB 16          // blocks per (j,b) for box-restricted kernels
#define TPB 256

// ---------------- static device scratch (zero-initialized at load) ----------------
__device__ float g_inv[3*BN*6];                 // inverse thetas: [which][b][6]
__device__ float g_bufA[BN*NPIX];               // pred_trans
__device__ float g_bufB[BN*NPIX];               // pred_rot
__device__ float g_rm2[NM*BN*NPIX];             // mask after g2 sample (zero outside boxes)
__device__ int4  g_srcpart[NM*8];               // per-j partial src bboxes
__device__ int4  g_box1[NM*BN];                 // stage-1 write box (r0,c0,h,w)
__device__ int4  g_box2[NM*BN];                 // stage-2 box (r0,c0,h,w)
__device__ float g_part1[NM*BN*KB*2];           // partial sums (new, mask)
__device__ float g_part3[NM*BN*KB*3];           // partial sums (tot, sx, sy)
__device__ float g_patch[BN*PATCH*PATCH];       // revise patch snapshot

// ---------------- helpers ----------------
__device__ __forceinline__ float bilin_sample(const float* __restrict__ s,
                                              float gx, float gy, int H, int W) {
    // torch grid_sample: bilinear, zero padding, align_corners=False
    float x = ((gx + 1.0f) * (float)W - 1.0f) * 0.5f;
    float y = ((gy + 1.0f) * (float)H - 1.0f) * 0.5f;
    float xf = floorf(x), yf = floorf(y);
    int x0 = (int)xf, y0 = (int)yf;
    float wx = x - xf, wy = y - yf;
    int x1 = x0 + 1, y1 = y0 + 1;
    bool xi0 = (x0 >= 0) && (x0 < W);
    bool xi1 = (x1 >= 0) && (x1 < W);
    bool yi0 = (y0 >= 0) && (y0 < H);
    bool yi1 = (y1 >= 0) && (y1 < H);
    float v00 = 0.f, v01 = 0.f, v10 = 0.f, v11 = 0.f;
    if (yi0) {
        const float* row = s + y0 * W;
        if (xi0) v00 = __ldg(row + x0);
        if (xi1) v01 = __ldg(row + x1);
    }
    if (yi1) {
        const float* row = s + y1 * W;
        if (xi0) v10 = __ldg(row + x0);
        if (xi1) v11 = __ldg(row + x1);
    }
    return (1.f - wx) * (1.f - wy) * v00 + wx * (1.f - wy) * v01
         + (1.f - wx) * wy * v10 + wx * wy * v11;
}

// ---------------- source mask bbox (partials) ----------------
__global__ void k_srcbox(const float* __restrict__ masks) {
    int j = blockIdx.y, seg = blockIdx.x;       // 8 segments per mask plane
    const float* m = masks + j * NPIX;
    int base = seg * (NPIX / 8);
    int rmin = 1 << 20, rmax = -1, cmin = 1 << 20, cmax = -1;
    for (int k = threadIdx.x; k < NPIX / 8; k += TPB) {
        int g = base + k;
        if (m[g] != 0.0f) {
            int r = g >> 9, c = g & 511;
            rmin = min(rmin, r); rmax = max(rmax, r);
            cmin = min(cmin, c); cmax = max(cmax, c);
        }
    }
    __shared__ int s0[TPB], s1[TPB], s2[TPB], s3[TPB];
    s0[threadIdx.x] = rmin; s1[threadIdx.x] = rmax;
    s2[threadIdx.x] = cmin; s3[threadIdx.x] = cmax;
    __syncthreads();
    for (int s = TPB / 2; s > 0; s >>= 1) {
        if (threadIdx.x < s) {
            s0[threadIdx.x] = min(s0[threadIdx.x], s0[threadIdx.x + s]);
            s1[threadIdx.x] = max(s1[threadIdx.x], s1[threadIdx.x + s]);
            s2[threadIdx.x] = min(s2[threadIdx.x], s2[threadIdx.x + s]);
            s3[threadIdx.x] = max(s3[threadIdx.x], s3[threadIdx.x + s]);
        }
        __syncthreads();
    }
    if (threadIdx.x == 0)
        g_srcpart[j * 8 + seg] = make_int4(s0[0], s1[0], s2[0], s3[0]);
}

// ---------------- affine preimage of a pixel rect ----------------
__device__ __forceinline__ void preimage_px(const float* th,
        float ya, float yb, float xa, float xb,
        int& ir0, int& ir1, int& ic0, int& ic1) {
    float gxa = (2.f * xa + 1.f) / 512.f - 1.f, gxb = (2.f * xb + 1.f) / 512.f - 1.f;
    float gya = (2.f * ya + 1.f) / 512.f - 1.f, gyb = (2.f * yb + 1.f) / 512.f - 1.f;
    float det = th[0] * th[4] - th[1] * th[3];
    float Xmin = 1e30f, Xmax = -1e30f, Ymin = 1e30f, Ymax = -1e30f;
    #pragma unroll
    for (int u = 0; u < 4; u++) {
        float gx = (u & 1) ? gxb : gxa;
        float gy = (u & 2) ? gyb : gya;
        float rx = gx - th[2], ry = gy - th[5];
        float X = ( th[4] * rx - th[1] * ry) / det;
        float Y = (-th[3] * rx + th[0] * ry) / det;
        Xmin = fminf(Xmin, X); Xmax = fmaxf(Xmax, X);
        Ymin = fminf(Ymin, Y); Ymax = fmaxf(Ymax, Y);
    }
    float jmin = ((Xmin + 1.f) * 512.f - 1.f) * 0.5f;
    float jmax = ((Xmax + 1.f) * 512.f - 1.f) * 0.5f;
    float imin = ((Ymin + 1.f) * 512.f - 1.f) * 0.5f;
    float imax = ((Ymax + 1.f) * 512.f - 1.f) * 0.5f;
    ir0 = max(0,   (int)floorf(imin) - 1);
    ir1 = min(511, (int)ceilf(imax) + 1);
    ic0 = max(0,   (int)floorf(jmin) - 1);
    ic1 = min(511, (int)ceilf(jmax) + 1);
}

// ---------------- K0: inverses THEN boxes (merged) ----------------
__global__ void k_invboxes(const float* __restrict__ sc, const float* __restrict__ ro,
                           const float* __restrict__ tr) {
    int t = threadIdx.x;
    if (t < 3 * BN) {
        int w = t / BN, b = t % BN;
        const float* src = (w == 0) ? sc : ((w == 1) ? ro : tr);
        const float* m = src + b * 6;
        float a = m[0], bb = m[1], c = m[2], d = m[3], e = m[4], f = m[5];
        float det = a * e - bb * d;
        float ia = e / det, ib = -bb / det, id = -d / det, ie = a / det;
        float ic  = -(ia * c + ib * f);
        float iff = -(id * c + ie * f);
        float* o = g_inv + t * 6;
        o[0] = ia; o[1] = ib; o[2] = ic; o[3] = id; o[4] = ie; o[5] = iff;
    }
    __syncthreads();
    if (t >= NM * BN) return;
    int j = t / BN, b = t % BN;
    int r0 = 1 << 20, r1 = -1, c0 = 1 << 20, c1 = -1;
    for (int k = 0; k < 8; k++) {
        int4 p = g_srcpart[j * 8 + k];
        r0 = min(r0, p.x); r1 = max(r1, p.y);
        c0 = min(c0, p.z); c1 = max(c1, p.w);
    }
    if (r1 < r0) {  // empty mask
        g_box1[t] = make_int4(0, 0, 0, 0);
        g_box2[t] = make_int4(0, 0, 0, 0);
        return;
    }
    // stage 1: sampled via g2 = inv(rotation)
    int a0, a1, b0, b1;
    preimage_px(g_inv + (BN + b) * 6,
                (float)r0 - 1.f, (float)r1 + 1.f,
                (float)c0 - 1.f, (float)c1 + 1.f, a0, a1, b0, b1);
    int w0 = max(0, a0 - 2), w1 = min(511, a1 + 2);
    int w2 = max(0, b0 - 2), w3 = min(511, b1 + 2);
    g_box1[t] = make_int4(w0, w2, w1 - w0 + 1, w3 - w2 + 1);
    // stage 2: sampled via g1 = inv(shear); target rect = stage-1 core box
    int d0, d1, e0, e1;
    preimage_px(g_inv + b * 6,
                (float)a0 - 1.f, (float)a1 + 1.f,
                (float)b0 - 1.f, (float)b1 + 1.f, d0, d1, e0, e1);
    d0 = max(0, d0 - 1); d1 = min(511, d1 + 1);
    e0 = max(0, e0 - 1); e1 = min(511, e1 + 1);
    g_box2[t] = make_int4(d0, e0, d1 - d0 + 1, e1 - e0 + 1);
}

// ---------------- K1: jax.image.resize linear, 4 outputs/thread ----------------
__global__ void k_resize4(const float* __restrict__ base, float* __restrict__ out) {
    int idx = blockIdx.x * blockDim.x + threadIdx.x;
    if (idx >= BN * NPIX / 4) return;
    int b = idx / (NPIX / 4), r4 = idx - b * (NPIX / 4);
    int i = r4 >> 7;
    int j0 = (r4 & 127) * 4;
    float fy = (i + 0.5f) * 0.25f - 0.5f;
    fy = fminf(fmaxf(fy, 0.f), 127.f);
    int y0 = (int)fy;
    float wy = fy - (float)y0;
    int y1 = min(y0 + 1, 127);
    const float* p = base + b * 128 * 128;
    const float* r0 = p + y0 * 128;
    const float* r1 = p + y1 * 128;
    float4 o;
    #pragma unroll
    for (int q = 0; q < 4; q++) {
        float fx = (j0 + q + 0.5f) * 0.25f - 0.5f;
        fx = fminf(fmaxf(fx, 0.f), 127.f);
        int x0 = (int)fx;
        float wx = fx - (float)x0;
        int x1 = min(x0 + 1, 127);
        float top = (1.f - wx) * __ldg(r0 + x0) + wx * __ldg(r0 + x1);
        float bot = (1.f - wx) * __ldg(r1 + x0) + wx * __ldg(r1 + x1);
        ((float*)&o)[q] = (1.f - wy) * top + wy * bot;
    }
    ((float4*)out)[idx] = o;
}

// ---------------- image warp, 2D-tiled: block (32,8) -> tile 128x8 px ----------------
__global__ void k_warp4t(const float* __restrict__ src, float* __restrict__ dst,
                         float* __restrict__ dst2, int thoff) {
    int b = blockIdx.z;
    int i = blockIdx.y * 8 + threadIdx.y;
    int j0 = (blockIdx.x * 32 + threadIdx.x) * 4;
    const float* th = g_inv + (thoff + b) * 6;
    float t0 = th[0], t1 = th[1], t2 = th[2], t3 = th[3], t4 = th[4], t5 = th[5];
    float Y = (float)(2 * i + 1) / 512.0f - 1.0f;
    const float* s = src + b * NPIX;
    float4 o;
    #pragma unroll
    for (int q = 0; q < 4; q++) {
        float X = (float)(2 * (j0 + q) + 1) / 512.0f - 1.0f;
        float gx = t0 * X + t1 * Y + t2;
        float gy = t3 * X + t4 * Y + t5;
        ((float*)&o)[q] = bilin_sample(s, gx, gy, UPD, UPD);
    }
    int idx4 = (b * NPIX + (i << 9) + j0) >> 2;
    ((float4*)dst)[idx4] = o;
    if (dst2) ((float4*)dst2)[idx4] = o;
}

// ---------------- mask stage 1 (box-restricted): mask_j -> g_rm2 via g2 ----------------
__global__ void k_mask1(const float* __restrict__ masks) {
    int jb = blockIdx.y;
    int j = jb / BN, b = jb % BN;
    int4 bx = g_box1[jb];
    int area = bx.z * bx.w;
    const float* th = g_inv + (BN + b) * 6;
    float t0 = th[0], t1 = th[1], t2 = th[2], t3 = th[3], t4 = th[4], t5 = th[5];
    const float* s = masks + j * NPIX;
    float* dst = g_rm2 + (size_t)jb * NPIX;
    for (int t = blockIdx.x * TPB + threadIdx.x; t < area; t += KB * TPB) {
        int i = bx.x + t / bx.w, jj = bx.y + t % bx.w;
        float X = (float)(2 * jj + 1) / 512.0f - 1.0f;
        float Y = (float)(2 * i + 1) / 512.0f - 1.0f;
        float gx = t0 * X + t1 * Y + t2;
        float gy = t3 * X + t4 * Y + t5;
        dst[(i << 9) + jj] = bilin_sample(s, gx, gy, UPD, UPD);
    }
}

// ---------------- mask stage 2 (box-restricted) FUSED with COM pass 1 ----------------
__global__ void k_mask2f(const float* __restrict__ img_all, float* __restrict__ out) {
    int jb = blockIdx.y;
    int b = jb % BN;
    int4 bx = g_box2[jb];
    int area = bx.z * bx.w;
    const float* th = g_inv + b * 6;   // inv(scaler_shear)
    float t0 = th[0], t1 = th[1], t2 = th[2], t3 = th[3], t4 = th[4], t5 = th[5];
    const float* src = g_rm2 + (size_t)jb * NPIX;
    const float* img = img_all + b * NPIX;
    float* dst = out + (size_t)jb * NPIX;
    float sn = 0.f, sm = 0.f;
    for (int t = blockIdx.x * TPB + threadIdx.x; t < area; t += KB * TPB) {
        int i = bx.x + t / bx.w, jj = bx.y + t % bx.w;
        float X = (float)(2 * jj + 1) / 512.0f - 1.0f;
        float Y = (float)(2 * i + 1) / 512.0f - 1.0f;
        float gx = t0 * X + t1 * Y + t2;
        float gy = t3 * X + t4 * Y + t5;
        float v = bilin_sample(src, gx, gy, UPD, UPD);
        int g = (i << 9) + jj;
        bool on = (v >= 0.5f);
        dst[g] = on ? 1.0f : 0.0f;
        if (on) { sn += img[g]; sm += 1.0f; }
    }
    __shared__ float sh1[TPB], sh2[TPB];
    sh1[threadIdx.x] = sn; sh2[threadIdx.x] = sm;
    __syncthreads();
    for (int s = TPB / 2; s > 0; s >>= 1) {
        if (threadIdx.x < s) {
            sh1[threadIdx.x] += sh1[threadIdx.x + s];
            sh2[threadIdx.x] += sh2[threadIdx.x + s];
        }
        __syncthreads();
    }
    if (threadIdx.x == 0) {
        int o = (jb * KB + blockIdx.x) * 2;
        g_part1[o] = sh1[0]; g_part1[o + 1] = sh2[0];
    }
}

// ---------------- COM pass 2 (box-restricted; threshold computed inline) ----------------
__global__ void k_p3(const float* __restrict__ pin, const float* __restrict__ mrot) {
    int jb = blockIdx.y;
    int b = jb % BN;
    __shared__ float sh_thr;
    if (threadIdx.x == 0) {
        float sn = 0.f, sm = 0.f;
        for (int k = 0; k < KB; k++) {             // identical order to old k_p2
            sn += g_part1[(jb * KB + k) * 2];
            sm += g_part1[(jb * KB + k) * 2 + 1];
        }
        sh_thr = (sn / fmaxf(sm, 1.0f)) * 1.5f;
    }
    __syncthreads();
    float thr = sh_thr;
    int4 bx = g_box2[jb];
    int area = bx.z * bx.w;
    const float* img = pin + b * NPIX;
    const float* m = mrot + (size_t)jb * NPIX;
    float st = 0.f, sx = 0.f, sy = 0.f;
    for (int t = blockIdx.x * TPB + threadIdx.x; t < area; t += KB * TPB) {
        int i = bx.x + t / bx.w, jj = bx.y + t % bx.w;
        int g = (i << 9) + jj;
        if (m[g] > 0.5f) {
            float nv = img[g];
            if (nv > thr) {
                st += nv;
                sx += nv * (float)i;
                sy += nv * (float)jj;
            }
        }
    }
    __shared__ float sh1[TPB], sh2[TPB], sh3[TPB];
    sh1[threadIdx.x] = st; sh2[threadIdx.x] = sx; sh3[threadIdx.x] = sy;
    __syncthreads();
    for (int s = TPB / 2; s > 0; s >>= 1) {
        if (threadIdx.x < s) {
            sh1[threadIdx.x] += sh1[threadIdx.x + s];
            sh2[threadIdx.x] += sh2[threadIdx.x + s];
            sh3[threadIdx.x] += sh3[threadIdx.x + s];
        }
        __syncthreads();
    }
    if (threadIdx.x == 0) {
        int o = (jb * KB + blockIdx.x) * 3;
        g_part3[o] = sh1[0]; g_part3[o + 1] = sh2[0]; g_part3[o + 2] = sh3[0];
    }
}

// ---------------- revise: one block per batch item, internal loop over j ----------------
__global__ void k_revise(float* __restrict__ rev, const float* __restrict__ adj) {
    int b = blockIdx.x;
    int tid = threadIdx.x;
    float a = adj[b];
    float* img = rev + b * NPIX;
    float* patch = g_patch + b * PATCH * PATCH;
    const float* th = g_inv + b * 6;  // inv(scaler_shear)
    __shared__ int sh_xy[2];
    for (int j = 0; j < NM; j++) {
        if (tid == 0) {
            float tot = 0.f, sx = 0.f, sy = 0.f;
            for (int k = 0; k < KB; k++) {
                int o = ((j * BN + b) * KB + k) * 3;
                tot += g_part3[o]; sx += g_part3[o + 1]; sy += g_part3[o + 2];
            }
            tot += 1e-8f;
            float cx = sx / tot, cy = sy / tot;
            int x0 = __float2int_rn(cx) - 60;            // round half to even
            int y0 = __float2int_rn(cy) - 60;
            x0 = min(max(x0, 0), UPD - PATCH);           // dynamic_slice clamping
            y0 = min(max(y0, 0), UPD - PATCH);
            sh_xy[0] = x0; sh_xy[1] = y0;
        }
        __syncthreads();
        int x0 = sh_xy[0], y0 = sh_xy[1];
        for (int t = tid; t < PATCH * PATCH; t += blockDim.x) {
            int p = t / PATCH, q = t - p * PATCH;
            float v = img[(x0 + p) * UPD + (y0 + q)];
            int dp = p - 60, dq = q - 60;
            if (dp * dp + dq * dq <= 16) v = v / a;
            patch[t] = v;
        }
        __syncthreads();
        for (int t = tid; t < PATCH * PATCH; t += blockDim.x) {
            int p = t / PATCH, q = t - p * PATCH;
            float X = (float)(2 * q + 1) / 120.0f - 1.0f;
            float Y = (float)(2 * p + 1) / 120.0f - 1.0f;
            float gx = th[0] * X + th[1] * Y + th[2];
            float gy = th[3] * X + th[4] * Y + th[5];
            float v = bilin_sample(patch, gx, gy, PATCH, PATCH);
            img[(x0 + p) * UPD + (y0 + q)] = v;
        }
        __syncthreads();
    }
}

// ---------------- launch ----------------
extern "C" void kernel_launch(void* const* d_in, const int* in_sizes, int n_in,
                              void* d_out, int out_size) {
    const float* base  = (const float*)d_in[0];  // (16,1,128,128)
    const float* sc    = (const float*)d_in[1];  // (16,2,3)
    const float* ro    = (const float*)d_in[2];  // (16,2,3)
    const float* tr    = (const float*)d_in[3];  // (16,2,3)
    const float* adj   = (const float*)d_in[4];  // (16,)
    const float* masks = (const float*)d_in[5];  // (4,512,512)
    float* out = (float*)d_out;
    float* seg0 = out;                           // base_inp    (16,1,512,512)
    float* seg1 = out + (size_t)BN * NPIX;       // pred_input
    float* seg2 = out + (size_t)2 * BN * NPIX;   // pred_revise
    float* seg3 = out + (size_t)3 * BN * NPIX;   // masks_rot (4,16,512,512) 0/1

    // DEVICE addresses of __device__ scratch (host-side symbol addresses route
    // over NVLink-C2C to host DRAM on GB300 — the round-2 regression).
    float *bufA, *bufB;
    cudaGetSymbolAddress((void**)&bufA, g_bufA);
    cudaGetSymbolAddress((void**)&bufB, g_bufB);

    int nblk_img4 = (BN * NPIX / 4 + TPB - 1) / TPB;
    dim3 wgrid(4, 64, BN), wblk(32, 8);

    k_srcbox<<<dim3(8, NM), TPB>>>(masks);
    k_invboxes<<<1, 64>>>(sc, ro, tr);
    cudaMemsetAsync(seg3, 0, (size_t)NM * BN * NPIX * sizeof(float));
    k_resize4<<<nblk_img4, TPB>>>(base, seg0);
    k_warp4t<<<wgrid, wblk>>>(seg0, bufA, nullptr, 2 * BN);   // inv(translation)
    k_warp4t<<<wgrid, wblk>>>(bufA, bufB, nullptr, 1 * BN);   // inv(rotation)
    k_warp4t<<<wgrid, wblk>>>(bufB, seg1, seg2, 0);           // inv(shear)
    k_mask1<<<dim3(KB, NM * BN), TPB>>>(masks);
    k_mask2f<<<dim3(KB, NM * BN), TPB>>>(seg1, seg3);
    k_p3<<<dim3(KB, NM * BN), TPB>>>(seg1, seg3);
    k_revise<<<BN, 512>>>(seg2, adj);
}

// round 6
// speedup vs baseline: 4.6541x; 1.0998x over previous
#include <cuda_runtime.h>
#include <math.h>

#define BN 16
#define UPD 512
#define NPIX (UPD*UPD)
#define PATCH 120
#define NM 4
#define TPB 256

// ---------------- static device scratch (zero-initialized at load) ----------------
__device__ float g_inv[3*BN*6];                 // inverse thetas: [which][b][6]
__device__ float g_bufA[BN*NPIX];               // pred_trans
__device__ float g_bufB[BN*NPIX];               // pred_rot
__device__ float g_rm2[NM*BN*NPIX];             // mask after g2 sample (zero outside boxes)
__device__ int4  g_srcpart[NM*8];               // per-j partial src bboxes
__device__ int4  g_box1[NM*BN];                 // stage-1 write box (r0,c0,h,w)
__device__ int4  g_box2[NM*BN];                 // stage-2 box (r0,c0,h,w)
__device__ float g_com[NM*BN*3];                // per (j,b): tot, sx, sy
__device__ float g_patch[BN*PATCH*PATCH];       // revise patch snapshot

// ---------------- helpers ----------------
__device__ __forceinline__ float bilin_sample(const float* __restrict__ s,
                                              float gx, float gy, int H, int W) {
    // torch grid_sample: bilinear, zero padding, align_corners=False
    float x = ((gx + 1.0f) * (float)W - 1.0f) * 0.5f;
    float y = ((gy + 1.0f) * (float)H - 1.0f) * 0.5f;
    float xf = floorf(x), yf = floorf(y);
    int x0 = (int)xf, y0 = (int)yf;
    float wx = x - xf, wy = y - yf;
    int x1 = x0 + 1, y1 = y0 + 1;
    bool xi0 = (x0 >= 0) && (x0 < W);
    bool xi1 = (x1 >= 0) && (x1 < W);
    bool yi0 = (y0 >= 0) && (y0 < H);
    bool yi1 = (y1 >= 0) && (y1 < H);
    float v00 = 0.f, v01 = 0.f, v10 = 0.f, v11 = 0.f;
    if (yi0) {
        const float* row = s + y0 * W;
        if (xi0) v00 = __ldg(row + x0);
        if (xi1) v01 = __ldg(row + x1);
    }
    if (yi1) {
        const float* row = s + y1 * W;
        if (xi0) v10 = __ldg(row + x0);
        if (xi1) v11 = __ldg(row + x1);
    }
    return (1.f - wx) * (1.f - wy) * v00 + wx * (1.f - wy) * v01
         + (1.f - wx) * wy * v10 + wx * wy * v11;
}

// ---------------- K0: 2x3 affine inverses ----------------
__global__ void k_inv(const float* __restrict__ sc, const float* __restrict__ ro,
                      const float* __restrict__ tr) {
    int t = threadIdx.x;
    if (t >= 3 * BN) return;
    int w = t / BN, b = t % BN;
    const float* src = (w == 0) ? sc : ((w == 1) ? ro : tr);
    const float* m = src + b * 6;
    float a = m[0], bb = m[1], c = m[2], d = m[3], e = m[4], f = m[5];
    float det = a * e - bb * d;
    float ia = e / det, ib = -bb / det, id = -d / det, ie = a / det;
    float ic  = -(ia * c + ib * f);
    float iff = -(id * c + ie * f);
    float* o = g_inv + t * 6;
    o[0] = ia; o[1] = ib; o[2] = ic; o[3] = id; o[4] = ie; o[5] = iff;
}

// ---------------- source mask bbox (partials) ----------------
__global__ void k_srcbox(const float* __restrict__ masks) {
    int j = blockIdx.y, seg = blockIdx.x;       // 8 segments per mask plane
    const float* m = masks + j * NPIX;
    int base = seg * (NPIX / 8);
    int rmin = 1 << 20, rmax = -1, cmin = 1 << 20, cmax = -1;
    for (int k = threadIdx.x; k < NPIX / 8; k += TPB) {
        int g = base + k;
        if (m[g] != 0.0f) {
            int r = g >> 9, c = g & 511;
            rmin = min(rmin, r); rmax = max(rmax, r);
            cmin = min(cmin, c); cmax = max(cmax, c);
        }
    }
    __shared__ int s0[TPB], s1[TPB], s2[TPB], s3[TPB];
    s0[threadIdx.x] = rmin; s1[threadIdx.x] = rmax;
    s2[threadIdx.x] = cmin; s3[threadIdx.x] = cmax;
    __syncthreads();
    for (int s = TPB / 2; s > 0; s >>= 1) {
        if (threadIdx.x < s) {
            s0[threadIdx.x] = min(s0[threadIdx.x], s0[threadIdx.x + s]);
            s1[threadIdx.x] = max(s1[threadIdx.x], s1[threadIdx.x + s]);
            s2[threadIdx.x] = min(s2[threadIdx.x], s2[threadIdx.x + s]);
            s3[threadIdx.x] = max(s3[threadIdx.x], s3[threadIdx.x + s]);
        }
        __syncthreads();
    }
    if (threadIdx.x == 0)
        g_srcpart[j * 8 + seg] = make_int4(s0[0], s1[0], s2[0], s3[0]);
}

// ---------------- affine preimage of a pixel rect ----------------
__device__ __forceinline__ void preimage_px(const float* th,
        float ya, float yb, float xa, float xb,
        int& ir0, int& ir1, int& ic0, int& ic1) {
    float gxa = (2.f * xa + 1.f) / 512.f - 1.f, gxb = (2.f * xb + 1.f) / 512.f - 1.f;
    float gya = (2.f * ya + 1.f) / 512.f - 1.f, gyb = (2.f * yb + 1.f) / 512.f - 1.f;
    float det = th[0] * th[4] - th[1] * th[3];
    float Xmin = 1e30f, Xmax = -1e30f, Ymin = 1e30f, Ymax = -1e30f;
    #pragma unroll
    for (int u = 0; u < 4; u++) {
        float gx = (u & 1) ? gxb : gxa;
        float gy = (u & 2) ? gyb : gya;
        float rx = gx - th[2], ry = gy - th[5];
        float X = ( th[4] * rx - th[1] * ry) / det;
        float Y = (-th[3] * rx + th[0] * ry) / det;
        Xmin = fminf(Xmin, X); Xmax = fmaxf(Xmax, X);
        Ymin = fminf(Ymin, Y); Ymax = fmaxf(Ymax, Y);
    }
    float jmin = ((Xmin + 1.f) * 512.f - 1.f) * 0.5f;
    float jmax = ((Xmax + 1.f) * 512.f - 1.f) * 0.5f;
    float imin = ((Ymin + 1.f) * 512.f - 1.f) * 0.5f;
    float imax = ((Ymax + 1.f) * 512.f - 1.f) * 0.5f;
    ir0 = max(0,   (int)floorf(imin) - 1);
    ir1 = min(511, (int)ceilf(imax) + 1);
    ic0 = max(0,   (int)floorf(jmin) - 1);
    ic1 = min(511, (int)ceilf(jmax) + 1);
}

// ---------------- per-(j,b) output boxes (needs g_inv + g_srcpart) ----------------
__global__ void k_boxes() {
    int t = threadIdx.x;
    if (t >= NM * BN) return;
    int j = t / BN, b = t % BN;
    int r0 = 1 << 20, r1 = -1, c0 = 1 << 20, c1 = -1;
    for (int k = 0; k < 8; k++) {
        int4 p = g_srcpart[j * 8 + k];
        r0 = min(r0, p.x); r1 = max(r1, p.y);
        c0 = min(c0, p.z); c1 = max(c1, p.w);
    }
    if (r1 < r0) {  // empty mask
        g_box1[t] = make_int4(0, 0, 0, 0);
        g_box2[t] = make_int4(0, 0, 0, 0);
        return;
    }
    // stage 1: sampled via g2 = inv(rotation)
    int a0, a1, b0, b1;
    preimage_px(g_inv + (BN + b) * 6,
                (float)r0 - 1.f, (float)r1 + 1.f,
                (float)c0 - 1.f, (float)c1 + 1.f, a0, a1, b0, b1);
    int w0 = max(0, a0 - 2), w1 = min(511, a1 + 2);
    int w2 = max(0, b0 - 2), w3 = min(511, b1 + 2);
    g_box1[t] = make_int4(w0, w2, w1 - w0 + 1, w3 - w2 + 1);
    // stage 2: sampled via g1 = inv(shear); target rect = stage-1 core box
    int d0, d1, e0, e1;
    preimage_px(g_inv + b * 6,
                (float)a0 - 1.f, (float)a1 + 1.f,
                (float)b0 - 1.f, (float)b1 + 1.f, d0, d1, e0, e1);
    d0 = max(0, d0 - 1); d1 = min(511, d1 + 1);
    e0 = max(0, e0 - 1); e1 = min(511, e1 + 1);
    g_box2[t] = make_int4(d0, e0, d1 - d0 + 1, e1 - e0 + 1);
}

// ---------------- K1: jax.image.resize linear, 4 outputs/thread ----------------
__global__ void k_resize4(const float* __restrict__ base, float* __restrict__ out) {
    int idx = blockIdx.x * blockDim.x + threadIdx.x;
    if (idx >= BN * NPIX / 4) return;
    int b = idx / (NPIX / 4), r4 = idx - b * (NPIX / 4);
    int i = r4 >> 7;
    int j0 = (r4 & 127) * 4;
    float fy = (i + 0.5f) * 0.25f - 0.5f;
    fy = fminf(fmaxf(fy, 0.f), 127.f);
    int y0 = (int)fy;
    float wy = fy - (float)y0;
    int y1 = min(y0 + 1, 127);
    const float* p = base + b * 128 * 128;
    const float* r0 = p + y0 * 128;
    const float* r1 = p + y1 * 128;
    float4 o;
    #pragma unroll
    for (int q = 0; q < 4; q++) {
        float fx = (j0 + q + 0.5f) * 0.25f - 0.5f;
        fx = fminf(fmaxf(fx, 0.f), 127.f);
        int x0 = (int)fx;
        float wx = fx - (float)x0;
        int x1 = min(x0 + 1, 127);
        float top = (1.f - wx) * __ldg(r0 + x0) + wx * __ldg(r0 + x1);
        float bot = (1.f - wx) * __ldg(r1 + x0) + wx * __ldg(r1 + x1);
        ((float*)&o)[q] = (1.f - wy) * top + wy * bot;
    }
    ((float4*)out)[idx] = o;
}

// ---------------- image warp, 2D-tiled: block (32,8) -> tile 128x8 px ----------------
__global__ void k_warp4t(const float* __restrict__ src, float* __restrict__ dst,
                         float* __restrict__ dst2, int thoff) {
    int b = blockIdx.z;
    int i = blockIdx.y * 8 + threadIdx.y;
    int j0 = (blockIdx.x * 32 + threadIdx.x) * 4;
    const float* th = g_inv + (thoff + b) * 6;
    float t0 = th[0], t1 = th[1], t2 = th[2], t3 = th[3], t4 = th[4], t5 = th[5];
    float Y = (float)(2 * i + 1) / 512.0f - 1.0f;
    const float* s = src + b * NPIX;
    float4 o;
    #pragma unroll
    for (int q = 0; q < 4; q++) {
        float X = (float)(2 * (j0 + q) + 1) / 512.0f - 1.0f;
        float gx = t0 * X + t1 * Y + t2;
        float gy = t3 * X + t4 * Y + t5;
        ((float*)&o)[q] = bilin_sample(s, gx, gy, UPD, UPD);
    }
    int idx4 = (b * NPIX + (i << 9) + j0) >> 2;
    ((float4*)dst)[idx4] = o;
    if (dst2) ((float4*)dst2)[idx4] = o;
}

// ---------------- FUSED mask pipeline: one block per (j,b) ----------------
// pass1: sample masks via g2 into g_rm2 box; pass2: sample g_rm2 via g1,
// threshold, write masks_rot + accumulate (sum img*m, sum m); in-block
// threshold; pass3: COM sums -> g_com. All reductions deterministic.
__global__ void k_maskfused(const float* __restrict__ masks,
                            const float* __restrict__ img_all,
                            float* __restrict__ mrot) {
    int jb = blockIdx.x;
    int j = jb / BN, b = jb % BN;
    int tid = threadIdx.x;
    const int NT = 512;
    __shared__ float sh1[NT], sh2[NT], sh3[NT];
    __shared__ float sh_thr;

    // ---- pass 1: mask_j -> g_rm2 (box1) via inv(rotation)
    {
        int4 bx = g_box1[jb];
        int area = bx.z * bx.w;
        const float* th = g_inv + (BN + b) * 6;
        float t0 = th[0], t1 = th[1], t2 = th[2], t3 = th[3], t4 = th[4], t5 = th[5];
        const float* s = masks + j * NPIX;
        float* dst = g_rm2 + (size_t)jb * NPIX;
        for (int t = tid; t < area; t += NT) {
            int i = bx.x + t / bx.w, jj = bx.y + t % bx.w;
            float X = (float)(2 * jj + 1) / 512.0f - 1.0f;
            float Y = (float)(2 * i + 1) / 512.0f - 1.0f;
            float gx = t0 * X + t1 * Y + t2;
            float gy = t3 * X + t4 * Y + t5;
            dst[(i << 9) + jj] = bilin_sample(s, gx, gy, UPD, UPD);
        }
    }
    __syncthreads();   // block-wide visibility of g_rm2 writes

    // ---- pass 2: g_rm2 -> masks_rot (box2) via inv(shear) + (sum img*m, sum m)
    int4 bx = g_box2[jb];
    int area = bx.z * bx.w;
    const float* th = g_inv + b * 6;
    float t0 = th[0], t1 = th[1], t2 = th[2], t3 = th[3], t4 = th[4], t5 = th[5];
    const float* src = g_rm2 + (size_t)jb * NPIX;
    const float* img = img_all + b * NPIX;
    float* dst = mrot + (size_t)jb * NPIX;
    float sn = 0.f, sm = 0.f;
    for (int t = tid; t < area; t += NT) {
        int i = bx.x + t / bx.w, jj = bx.y + t % bx.w;
        float X = (float)(2 * jj + 1) / 512.0f - 1.0f;
        float Y = (float)(2 * i + 1) / 512.0f - 1.0f;
        float gx = t0 * X + t1 * Y + t2;
        float gy = t3 * X + t4 * Y + t5;
        float v = bilin_sample(src, gx, gy, UPD, UPD);
        int g = (i << 9) + jj;
        bool on = (v >= 0.5f);
        dst[g] = on ? 1.0f : 0.0f;
        if (on) { sn += img[g]; sm += 1.0f; }
    }
    sh1[tid] = sn; sh2[tid] = sm;
    __syncthreads();
    for (int s = NT / 2; s > 0; s >>= 1) {
        if (tid < s) {
            sh1[tid] += sh1[tid + s];
            sh2[tid] += sh2[tid + s];
        }
        __syncthreads();
    }
    if (tid == 0) sh_thr = (sh1[0] / fmaxf(sh2[0], 1.0f)) * 1.5f;
    __syncthreads();
    float thr = sh_thr;

    // ---- pass 3: COM sums
    float st = 0.f, sx = 0.f, sy = 0.f;
    for (int t = tid; t < area; t += NT) {
        int i = bx.x + t / bx.w, jj = bx.y + t % bx.w;
        int g = (i << 9) + jj;
        if (dst[g] > 0.5f) {
            float nv = img[g];
            if (nv > thr) {
                st += nv;
                sx += nv * (float)i;
                sy += nv * (float)jj;
            }
        }
    }
    sh1[tid] = st; sh2[tid] = sx; sh3[tid] = sy;
    __syncthreads();
    for (int s = NT / 2; s > 0; s >>= 1) {
        if (tid < s) {
            sh1[tid] += sh1[tid + s];
            sh2[tid] += sh2[tid + s];
            sh3[tid] += sh3[tid + s];
        }
        __syncthreads();
    }
    if (tid == 0) {
        g_com[jb * 3 + 0] = sh1[0];
        g_com[jb * 3 + 1] = sh2[0];
        g_com[jb * 3 + 2] = sh3[0];
    }
}

// ---------------- revise: one block per batch item, internal loop over j ----------------
__global__ void k_revise(float* __restrict__ rev, const float* __restrict__ adj) {
    int b = blockIdx.x;
    int tid = threadIdx.x;
    float a = adj[b];
    float* img = rev + b * NPIX;
    float* patch = g_patch + b * PATCH * PATCH;
    const float* th = g_inv + b * 6;  // inv(scaler_shear)
    __shared__ int sh_xy[2];
    for (int j = 0; j < NM; j++) {
        if (tid == 0) {
            int o = (j * BN + b) * 3;
            float tot = g_com[o] + 1e-8f;
            float cx = g_com[o + 1] / tot, cy = g_com[o + 2] / tot;
            int x0 = __float2int_rn(cx) - 60;            // round half to even
            int y0 = __float2int_rn(cy) - 60;
            x0 = min(max(x0, 0), UPD - PATCH);           // dynamic_slice clamping
            y0 = min(max(y0, 0), UPD - PATCH);
            sh_xy[0] = x0; sh_xy[1] = y0;
        }
        __syncthreads();
        int x0 = sh_xy[0], y0 = sh_xy[1];
        for (int t = tid; t < PATCH * PATCH; t += blockDim.x) {
            int p = t / PATCH, q = t - p * PATCH;
            float v = img[(x0 + p) * UPD + (y0 + q)];
            int dp = p - 60, dq = q - 60;
            if (dp * dp + dq * dq <= 16) v = v / a;
            patch[t] = v;
        }
        __syncthreads();
        for (int t = tid; t < PATCH * PATCH; t += blockDim.x) {
            int p = t / PATCH, q = t - p * PATCH;
            float X = (float)(2 * q + 1) / 120.0f - 1.0f;
            float Y = (float)(2 * p + 1) / 120.0f - 1.0f;
            float gx = th[0] * X + th[1] * Y + th[2];
            float gy = th[3] * X + th[4] * Y + th[5];
            float v = bilin_sample(patch, gx, gy, PATCH, PATCH);
            img[(x0 + p) * UPD + (y0 + q)] = v;
        }
        __syncthreads();
    }
}

// ---------------- launch ----------------
extern "C" void kernel_launch(void* const* d_in, const int* in_sizes, int n_in,
                              void* d_out, int out_size) {
    const float* base  = (const float*)d_in[0];  // (16,1,128,128)
    const float* sc    = (const float*)d_in[1];  // (16,2,3)
    const float* ro    = (const float*)d_in[2];  // (16,2,3)
    const float* tr    = (const float*)d_in[3];  // (16,2,3)
    const float* adj   = (const float*)d_in[4];  // (16,)
    const float* masks = (const float*)d_in[5];  // (4,512,512)
    float* out = (float*)d_out;
    float* seg0 = out;                           // base_inp    (16,1,512,512)
    float* seg1 = out + (size_t)BN * NPIX;       // pred_input
    float* seg2 = out + (size_t)2 * BN * NPIX;   // pred_revise
    float* seg3 = out + (size_t)3 * BN * NPIX;   // masks_rot (4,16,512,512) 0/1

    // DEVICE addresses of __device__ scratch (host symbol addresses route over
    // NVLink-C2C on GB300 — round-2 regression).
    float *bufA, *bufB;
    cudaGetSymbolAddress((void**)&bufA, g_bufA);
    cudaGetSymbolAddress((void**)&bufB, g_bufB);

    int nblk_img4 = (BN * NPIX / 4 + TPB - 1) / TPB;
    dim3 wgrid(4, 64, BN), wblk(32, 8);

    // Side stream for the mask-prep branch (memset/srcbox/boxes) so the graph
    // runs it concurrently with the image chain. Created fresh each call
    // (only ~2 calls happen: correctness + capture); never destroyed while a
    // capture may be active.
    cudaStream_t s1;
    cudaStreamCreateWithFlags(&s1, cudaStreamNonBlocking);
    cudaEvent_t evRoot, evInv, evS1;
    cudaEventCreateWithFlags(&evRoot, cudaEventDisableTiming);
    cudaEventCreateWithFlags(&evInv, cudaEventDisableTiming);
    cudaEventCreateWithFlags(&evS1, cudaEventDisableTiming);

    // fork
    cudaEventRecord(evRoot, 0);
    cudaStreamWaitEvent(s1, evRoot, 0);

    // main chain (default stream)
    k_inv<<<1, 64>>>(sc, ro, tr);
    cudaEventRecord(evInv, 0);
    k_resize4<<<nblk_img4, TPB>>>(base, seg0);
    k_warp4t<<<wgrid, wblk>>>(seg0, bufA, nullptr, 2 * BN);   // inv(translation)
    k_warp4t<<<wgrid, wblk>>>(bufA, bufB, nullptr, 1 * BN);   // inv(rotation)
    k_warp4t<<<wgrid, wblk>>>(bufB, seg1, seg2, 0);           // inv(shear)

    // side branch: masks_rot background + boxes
    cudaMemsetAsync(seg3, 0, (size_t)NM * BN * NPIX * sizeof(float), s1);
    k_srcbox<<<dim3(8, NM), TPB, 0, s1>>>(masks);
    cudaStreamWaitEvent(s1, evInv, 0);                         // boxes need g_inv
    k_boxes<<<1, 64, 0, s1>>>();
    cudaEventRecord(evS1, s1);

    // join, then fused mask pipeline + revise
    cudaStreamWaitEvent(0, evS1, 0);
    k_maskfused<<<NM * BN, 512>>>(masks, seg1, seg3);
    k_revise<<<BN, 512>>>(seg2, adj);
}

// round 8
// speedup vs baseline: 5.3263x; 1.1444x over previous
#include <cuda_runtime.h>
#include <math.h>

#define BN 16
#define UPD 512
#define NPIX (UPD*UPD)
#define PATCH 120
#define NM 4
#define TPB 256

// ---------------- static device scratch (zero-initialized at load) ----------------
__device__ float g_inv[3*BN*6];                 // inverse thetas: [which][b][6]
__device__ float g_bufA[BN*NPIX];               // pred_trans
__device__ float g_bufB[BN*NPIX];               // pred_rot
__device__ float g_rm2[NM*BN*NPIX];             // mask after g2 sample (zero outside boxes)
__device__ int4  g_srcpart[NM*8];               // per-j partial src bboxes
__device__ int4  g_box1[NM*BN];                 // stage-1 write box (r0,c0,h,w)
__device__ int4  g_box2[NM*BN];                 // stage-2 box (r0,c0,h,w)
__device__ float g_com[NM*BN*3];                // per (j,b): tot, sx, sy

// ---------------- helpers ----------------
__device__ __forceinline__ float bilin_sample(const float* __restrict__ s,
                                              float gx, float gy, int H, int W) {
    // torch grid_sample: bilinear, zero padding, align_corners=False
    float x = ((gx + 1.0f) * (float)W - 1.0f) * 0.5f;
    float y = ((gy + 1.0f) * (float)H - 1.0f) * 0.5f;
    float xf = floorf(x), yf = floorf(y);
    int x0 = (int)xf, y0 = (int)yf;
    float wx = x - xf, wy = y - yf;
    int x1 = x0 + 1, y1 = y0 + 1;
    bool xi0 = (x0 >= 0) && (x0 < W);
    bool xi1 = (x1 >= 0) && (x1 < W);
    bool yi0 = (y0 >= 0) && (y0 < H);
    bool yi1 = (y1 >= 0) && (y1 < H);
    float v00 = 0.f, v01 = 0.f, v10 = 0.f, v11 = 0.f;
    if (yi0) {
        const float* row = s + y0 * W;
        if (xi0) v00 = __ldg(row + x0);
        if (xi1) v01 = __ldg(row + x1);
    }
    if (yi1) {
        const float* row = s + y1 * W;
        if (xi0) v10 = __ldg(row + x0);
        if (xi1) v11 = __ldg(row + x1);
    }
    return (1.f - wx) * (1.f - wy) * v00 + wx * (1.f - wy) * v01
         + (1.f - wx) * wy * v10 + wx * wy * v11;
}

// ---------------- K0: 2x3 affine inverses ----------------
__global__ void k_inv(const float* __restrict__ sc, const float* __restrict__ ro,
                      const float* __restrict__ tr) {
    int t = threadIdx.x;
    if (t >= 3 * BN) return;
    int w = t / BN, b = t % BN;
    const float* src = (w == 0) ? sc : ((w == 1) ? ro : tr);
    const float* m = src + b * 6;
    float a = m[0], bb = m[1], c = m[2], d = m[3], e = m[4], f = m[5];
    float det = a * e - bb * d;
    float ia = e / det, ib = -bb / det, id = -d / det, ie = a / det;
    float ic  = -(ia * c + ib * f);
    float iff = -(id * c + ie * f);
    float* o = g_inv + t * 6;
    o[0] = ia; o[1] = ib; o[2] = ic; o[3] = id; o[4] = ie; o[5] = iff;
}

// ---------------- source mask bbox (partials) ----------------
__global__ void k_srcbox(const float* __restrict__ masks) {
    int j = blockIdx.y, seg = blockIdx.x;
    const float* m = masks + j * NPIX;
    int base = seg * (NPIX / 8);
    int rmin = 1 << 20, rmax = -1, cmin = 1 << 20, cmax = -1;
    for (int k = threadIdx.x; k < NPIX / 8; k += TPB) {
        int g = base + k;
        if (m[g] != 0.0f) {
            int r = g >> 9, c = g & 511;
            rmin = min(rmin, r); rmax = max(rmax, r);
            cmin = min(cmin, c); cmax = max(cmax, c);
        }
    }
    __shared__ int s0[TPB], s1[TPB], s2[TPB], s3[TPB];
    s0[threadIdx.x] = rmin; s1[threadIdx.x] = rmax;
    s2[threadIdx.x] = cmin; s3[threadIdx.x] = cmax;
    __syncthreads();
    for (int s = TPB / 2; s > 0; s >>= 1) {
        if (threadIdx.x < s) {
            s0[threadIdx.x] = min(s0[threadIdx.x], s0[threadIdx.x + s]);
            s1[threadIdx.x] = max(s1[threadIdx.x], s1[threadIdx.x + s]);
            s2[threadIdx.x] = min(s2[threadIdx.x], s2[threadIdx.x + s]);
            s3[threadIdx.x] = max(s3[threadIdx.x], s3[threadIdx.x + s]);
        }
        __syncthreads();
    }
    if (threadIdx.x == 0)
        g_srcpart[j * 8 + seg] = make_int4(s0[0], s1[0], s2[0], s3[0]);
}

// ---------------- affine preimage of a pixel rect ----------------
__device__ __forceinline__ void preimage_px(const float* th,
        float ya, float yb, float xa, float xb,
        int& ir0, int& ir1, int& ic0, int& ic1) {
    float gxa = (2.f * xa + 1.f) / 512.f - 1.f, gxb = (2.f * xb + 1.f) / 512.f - 1.f;
    float gya = (2.f * ya + 1.f) / 512.f - 1.f, gyb = (2.f * yb + 1.f) / 512.f - 1.f;
    float det = th[0] * th[4] - th[1] * th[3];
    float Xmin = 1e30f, Xmax = -1e30f, Ymin = 1e30f, Ymax = -1e30f;
    #pragma unroll
    for (int u = 0; u < 4; u++) {
        float gx = (u & 1) ? gxb : gxa;
        float gy = (u & 2) ? gyb : gya;
        float rx = gx - th[2], ry = gy - th[5];
        float X = ( th[4] * rx - th[1] * ry) / det;
        float Y = (-th[3] * rx + th[0] * ry) / det;
        Xmin = fminf(Xmin, X); Xmax = fmaxf(Xmax, X);
        Ymin = fminf(Ymin, Y); Ymax = fmaxf(Ymax, Y);
    }
    float jmin = ((Xmin + 1.f) * 512.f - 1.f) * 0.5f;
    float jmax = ((Xmax + 1.f) * 512.f - 1.f) * 0.5f;
    float imin = ((Ymin + 1.f) * 512.f - 1.f) * 0.5f;
    float imax = ((Ymax + 1.f) * 512.f - 1.f) * 0.5f;
    ir0 = max(0,   (int)floorf(imin) - 1);
    ir1 = min(511, (int)ceilf(imax) + 1);
    ic0 = max(0,   (int)floorf(jmin) - 1);
    ic1 = min(511, (int)ceilf(jmax) + 1);
}

// ---------------- per-(j,b) output boxes (needs g_inv + g_srcpart) ----------------
__global__ void k_boxes() {
    int t = threadIdx.x;
    if (t >= NM * BN) return;
    int j = t / BN, b = t % BN;
    int r0 = 1 << 20, r1 = -1, c0 = 1 << 20, c1 = -1;
    for (int k = 0; k < 8; k++) {
        int4 p = g_srcpart[j * 8 + k];
        r0 = min(r0, p.x); r1 = max(r1, p.y);
        c0 = min(c0, p.z); c1 = max(c1, p.w);
    }
    if (r1 < r0) {
        g_box1[t] = make_int4(0, 0, 0, 0);
        g_box2[t] = make_int4(0, 0, 0, 0);
        return;
    }
    int a0, a1, b0, b1;
    preimage_px(g_inv + (BN + b) * 6,
                (float)r0 - 1.f, (float)r1 + 1.f,
                (float)c0 - 1.f, (float)c1 + 1.f, a0, a1, b0, b1);
    int w0 = max(0, a0 - 2), w1 = min(511, a1 + 2);
    int w2 = max(0, b0 - 2), w3 = min(511, b1 + 2);
    g_box1[t] = make_int4(w0, w2, w1 - w0 + 1, w3 - w2 + 1);
    int d0, d1, e0, e1;
    preimage_px(g_inv + b * 6,
                (float)a0 - 1.f, (float)a1 + 1.f,
                (float)b0 - 1.f, (float)b1 + 1.f, d0, d1, e0, e1);
    d0 = max(0, d0 - 1); d1 = min(511, d1 + 1);
    e0 = max(0, e0 - 1); e1 = min(511, e1 + 1);
    g_box2[t] = make_int4(d0, e0, d1 - d0 + 1, e1 - e0 + 1);
}

// ---------------- K1: jax.image.resize linear, 4 outputs/thread ----------------
__global__ void k_resize4(const float* __restrict__ base, float* __restrict__ out) {
    int idx = blockIdx.x * blockDim.x + threadIdx.x;
    if (idx >= BN * NPIX / 4) return;
    int b = idx / (NPIX / 4), r4 = idx - b * (NPIX / 4);
    int i = r4 >> 7;
    int j0 = (r4 & 127) * 4;
    float fy = (i + 0.5f) * 0.25f - 0.5f;
    fy = fminf(fmaxf(fy, 0.f), 127.f);
    int y0 = (int)fy;
    float wy = fy - (float)y0;
    int y1 = min(y0 + 1, 127);
    const float* p = base + b * 128 * 128;
    const float* r0 = p + y0 * 128;
    const float* r1 = p + y1 * 128;
    float4 o;
    #pragma unroll
    for (int q = 0; q < 4; q++) {
        float fx = (j0 + q + 0.5f) * 0.25f - 0.5f;
        fx = fminf(fmaxf(fx, 0.f), 127.f);
        int x0 = (int)fx;
        float wx = fx - (float)x0;
        int x1 = min(x0 + 1, 127);
        float top = (1.f - wx) * __ldg(r0 + x0) + wx * __ldg(r0 + x1);
        float bot = (1.f - wx) * __ldg(r1 + x0) + wx * __ldg(r1 + x1);
        ((float*)&o)[q] = (1.f - wy) * top + wy * bot;
    }
    ((float4*)out)[idx] = o;
}

// ---------------- image warp, 8 px/thread ----------------
__global__ void k_warp8(const float* __restrict__ src, float* __restrict__ dst,
                        float* __restrict__ dst2, int thoff) {
    int b = blockIdx.z;
    int i = blockIdx.y * 8 + threadIdx.y;
    int j0 = (blockIdx.x * 32 + threadIdx.x) * 8;
    const float* th = g_inv + (thoff + b) * 6;
    float t0 = th[0], t1 = th[1], t2 = th[2], t3 = th[3], t4 = th[4], t5 = th[5];
    float Y = (float)(2 * i + 1) / 512.0f - 1.0f;
    const float* s = src + b * NPIX;
    float4 o0, o1;
    #pragma unroll
    for (int q = 0; q < 8; q++) {
        float X = (float)(2 * (j0 + q) + 1) / 512.0f - 1.0f;
        float gx = t0 * X + t1 * Y + t2;
        float gy = t3 * X + t4 * Y + t5;
        float v = bilin_sample(s, gx, gy, UPD, UPD);
        if (q < 4) ((float*)&o0)[q] = v; else ((float*)&o1)[q - 4] = v;
    }
    int idx4 = (b * NPIX + (i << 9) + j0) >> 2;
    ((float4*)dst)[idx4] = o0;
    ((float4*)dst)[idx4 + 1] = o1;
    if (dst2) {
        ((float4*)dst2)[idx4] = o0;
        ((float4*)dst2)[idx4 + 1] = o1;
    }
}

// ---------------- mask stage 1 (box-restricted, side stream) ----------------
__global__ void k_mask1(const float* __restrict__ masks) {
    int jb = blockIdx.y;
    int j = jb / BN, b = jb % BN;
    int4 bx = g_box1[jb];
    int area = bx.z * bx.w;
    const float* th = g_inv + (BN + b) * 6;
    float t0 = th[0], t1 = th[1], t2 = th[2], t3 = th[3], t4 = th[4], t5 = th[5];
    const float* s = masks + j * NPIX;
    float* dst = g_rm2 + (size_t)jb * NPIX;
    for (int t = blockIdx.x * TPB + threadIdx.x; t < area; t += 8 * TPB) {
        int i = bx.x + t / bx.w, jj = bx.y + t % bx.w;
        float X = (float)(2 * jj + 1) / 512.0f - 1.0f;
        float Y = (float)(2 * i + 1) / 512.0f - 1.0f;
        float gx = t0 * X + t1 * Y + t2;
        float gy = t3 * X + t4 * Y + t5;
        dst[(i << 9) + jj] = bilin_sample(s, gx, gy, UPD, UPD);
    }
}

// ---------------- FUSED mask stage 2 + threshold + COM: one block per (j,b) ----------------
__global__ void k_mask23(const float* __restrict__ img_all, float* __restrict__ mrot) {
    int jb = blockIdx.x;
    int b = jb % BN;
    int tid = threadIdx.x;
    const int NT = 1024;
    __shared__ float sh1[NT], sh2[NT], sh3[NT];
    __shared__ float sh_thr;

    int4 bx = g_box2[jb];
    int area = bx.z * bx.w;
    const float* th = g_inv + b * 6;
    float t0 = th[0], t1 = th[1], t2 = th[2], t3 = th[3], t4 = th[4], t5 = th[5];
    const float* src = g_rm2 + (size_t)jb * NPIX;
    const float* img = img_all + b * NPIX;
    float* dst = mrot + (size_t)jb * NPIX;
    float sn = 0.f, sm = 0.f;
    for (int t = tid; t < area; t += NT) {
        int i = bx.x + t / bx.w, jj = bx.y + t % bx.w;
        float X = (float)(2 * jj + 1) / 512.0f - 1.0f;
        float Y = (float)(2 * i + 1) / 512.0f - 1.0f;
        float gx = t0 * X + t1 * Y + t2;
        float gy = t3 * X + t4 * Y + t5;
        float v = bilin_sample(src, gx, gy, UPD, UPD);
        int g = (i << 9) + jj;
        bool on = (v >= 0.5f);
        dst[g] = on ? 1.0f : 0.0f;
        if (on) { sn += img[g]; sm += 1.0f; }
    }
    sh1[tid] = sn; sh2[tid] = sm;
    __syncthreads();
    for (int s = NT / 2; s > 0; s >>= 1) {
        if (tid < s) { sh1[tid] += sh1[tid + s]; sh2[tid] += sh2[tid + s]; }
        __syncthreads();
    }
    if (tid == 0) sh_thr = (sh1[0] / fmaxf(sh2[0], 1.0f)) * 1.5f;
    __syncthreads();
    float thr = sh_thr;

    float st = 0.f, sx = 0.f, sy = 0.f;
    for (int t = tid; t < area; t += NT) {
        int i = bx.x + t / bx.w, jj = bx.y + t % bx.w;
        int g = (i << 9) + jj;
        if (dst[g] > 0.5f) {
            float nv = img[g];
            if (nv > thr) {
                st += nv;
                sx += nv * (float)i;
                sy += nv * (float)jj;
            }
        }
    }
    sh1[tid] = st; sh2[tid] = sx; sh3[tid] = sy;
    __syncthreads();
    for (int s = NT / 2; s > 0; s >>= 1) {
        if (tid < s) {
            sh1[tid] += sh1[tid + s];
            sh2[tid] += sh2[tid + s];
            sh3[tid] += sh3[tid + s];
        }
        __syncthreads();
    }
    if (tid == 0) {
        g_com[jb * 3 + 0] = sh1[0];
        g_com[jb * 3 + 1] = sh2[0];
        g_com[jb * 3 + 2] = sh3[0];
    }
}

// ---------------- revise: one block per batch item; patch in dynamic smem ----------------
__global__ void k_revise(float* __restrict__ rev, const float* __restrict__ adj) {
    extern __shared__ float patch[];   // PATCH*PATCH floats = 57.6KB
    int b = blockIdx.x;
    int tid = threadIdx.x;
    float a = adj[b];
    float* img = rev + b * NPIX;
    const float* th = g_inv + b * 6;  // inv(scaler_shear)
    __shared__ int sh_xy[2];
    for (int j = 0; j < NM; j++) {
        if (tid == 0) {
            int o = (j * BN + b) * 3;
            float tot = g_com[o] + 1e-8f;
            float cx = g_com[o + 1] / tot, cy = g_com[o + 2] / tot;
            int x0 = __float2int_rn(cx) - 60;            // round half to even
            int y0 = __float2int_rn(cy) - 60;
            x0 = min(max(x0, 0), UPD - PATCH);           // dynamic_slice clamping
            y0 = min(max(y0, 0), UPD - PATCH);
            sh_xy[0] = x0; sh_xy[1] = y0;
        }
        __syncthreads();
        int x0 = sh_xy[0], y0 = sh_xy[1];
        for (int t = tid; t < PATCH * PATCH; t += blockDim.x) {
            int p = t / PATCH, q = t - p * PATCH;
            float v = img[(x0 + p) * UPD + (y0 + q)];
            int dp = p - 60, dq = q - 60;
            if (dp * dp + dq * dq <= 16) v = v / a;
            patch[t] = v;
        }
        __syncthreads();
        for (int t = tid; t < PATCH * PATCH; t += blockDim.x) {
            int p = t / PATCH, q = t - p * PATCH;
            float X = (float)(2 * q + 1) / 120.0f - 1.0f;
            float Y = (float)(2 * p + 1) / 120.0f - 1.0f;
            float gx = th[0] * X + th[1] * Y + th[2];
            float gy = th[3] * X + th[4] * Y + th[5];
            float x = ((gx + 1.0f) * 120.0f - 1.0f) * 0.5f;
            float y = ((gy + 1.0f) * 120.0f - 1.0f) * 0.5f;
            float xf = floorf(x), yf = floorf(y);
            int xx0 = (int)xf, yy0 = (int)yf;
            float wx = x - xf, wy = y - yf;
            int xx1 = xx0 + 1, yy1 = yy0 + 1;
            bool xi0 = (xx0 >= 0) && (xx0 < PATCH);
            bool xi1 = (xx1 >= 0) && (xx1 < PATCH);
            bool yi0 = (yy0 >= 0) && (yy0 < PATCH);
            bool yi1 = (yy1 >= 0) && (yy1 < PATCH);
            float v00 = (yi0 && xi0) ? patch[yy0 * PATCH + xx0] : 0.f;
            float v01 = (yi0 && xi1) ? patch[yy0 * PATCH + xx1] : 0.f;
            float v10 = (yi1 && xi0) ? patch[yy1 * PATCH + xx0] : 0.f;
            float v11 = (yi1 && xi1) ? patch[yy1 * PATCH + xx1] : 0.f;
            float v = (1.f - wx) * (1.f - wy) * v00 + wx * (1.f - wy) * v01
                    + (1.f - wx) * wy * v10 + wx * wy * v11;
            img[(x0 + p) * UPD + (y0 + q)] = v;
        }
        __syncthreads();
    }
}

// ---------------- launch ----------------
extern "C" void kernel_launch(void* const* d_in, const int* in_sizes, int n_in,
                              void* d_out, int out_size) {
    const float* base  = (const float*)d_in[0];
    const float* sc    = (const float*)d_in[1];
    const float* ro    = (const float*)d_in[2];
    const float* tr    = (const float*)d_in[3];
    const float* adj   = (const float*)d_in[4];
    const float* masks = (const float*)d_in[5];
    float* out = (float*)d_out;
    float* seg0 = out;                           // base_inp
    float* seg1 = out + (size_t)BN * NPIX;       // pred_input
    float* seg2 = out + (size_t)2 * BN * NPIX;   // pred_revise
    float* seg3 = out + (size_t)3 * BN * NPIX;   // masks_rot

    float *bufA, *bufB;
    cudaGetSymbolAddress((void**)&bufA, g_bufA);
    cudaGetSymbolAddress((void**)&bufB, g_bufB);

    // One-time resource setup on the FIRST (uncaptured) call. Reused on the
    // capture call so no driver allocations happen during/after capture
    // (round-7 failure: per-call stream/event creation left 2MB live at
    // graph teardown).
    static cudaStream_t s1 = nullptr;
    static cudaEvent_t evRoot, evInv, evS1;
    static bool init_done = false;
    if (!init_done) {
        cudaFuncSetAttribute(k_revise, cudaFuncAttributeMaxDynamicSharedMemorySize,
                             PATCH * PATCH * (int)sizeof(float));
        cudaStreamCreateWithFlags(&s1, cudaStreamNonBlocking);
        cudaEventCreateWithFlags(&evRoot, cudaEventDisableTiming);
        cudaEventCreateWithFlags(&evInv, cudaEventDisableTiming);
        cudaEventCreateWithFlags(&evS1, cudaEventDisableTiming);
        init_done = true;
    }

    int nblk_img4 = (BN * NPIX / 4 + TPB - 1) / TPB;
    dim3 wgrid8(2, 64, BN), wblk(32, 8);

    // fork
    cudaEventRecord(evRoot, 0);
    cudaStreamWaitEvent(s1, evRoot, 0);

    // main chain (default stream)
    k_inv<<<1, 64>>>(sc, ro, tr);
    cudaEventRecord(evInv, 0);
    k_resize4<<<nblk_img4, TPB>>>(base, seg0);
    k_warp8<<<wgrid8, wblk>>>(seg0, bufA, nullptr, 2 * BN);     // inv(translation)
    k_warp8<<<wgrid8, wblk>>>(bufA, bufB, nullptr, 1 * BN);     // inv(rotation)
    k_warp8<<<wgrid8, wblk>>>(bufB, seg1, seg2, 0);             // inv(shear)

    // side branch s1: memset + srcbox + boxes + mask1 (independent of image chain)
    cudaMemsetAsync(seg3, 0, (size_t)NM * BN * NPIX * sizeof(float), s1);
    k_srcbox<<<dim3(8, NM), TPB, 0, s1>>>(masks);
    cudaStreamWaitEvent(s1, evInv, 0);
    k_boxes<<<1, 64, 0, s1>>>();
    k_mask1<<<dim3(8, NM * BN), TPB, 0, s1>>>(masks);
    cudaEventRecord(evS1, s1);

    // join, fused mask stage2+COM, revise
    cudaStreamWaitEvent(0, evS1, 0);
    k_mask23<<<NM * BN, 1024>>>(seg1, seg3);
    k_revise<<<BN, 1024, PATCH * PATCH * sizeof(float)>>>(seg2, adj);
}

// round 9
// speedup vs baseline: 5.9178x; 1.1111x over previous
#include <cuda_runtime.h>
#include <math.h>

#define BN 16
#define UPD 512
#define NPIX (UPD*UPD)
#define PATCH 120
#define NM 4
#define TPB 256

// ---------------- static device scratch (zero-initialized at load) ----------------
__device__ float g_inv[3*BN*6];                 // inverse thetas: [which][b][6]
__device__ float g_bufA[BN*NPIX];               // pred_trans
__device__ float g_bufB[BN*NPIX];               // pred_rot
__device__ float g_rm2[NM*BN*NPIX];             // mask after g2 sample (zero outside boxes)
__device__ int4  g_srcpart[NM*8];               // per-j partial src bboxes
__device__ int4  g_box1[NM*BN];                 // stage-1 write box (r0,c0,h,w)
__device__ int4  g_box2[NM*BN];                 // stage-2 box (r0,c0,h,w)
__device__ float g_com[NM*BN*3];                // per (j,b): tot, sx, sy

// ---------------- helpers ----------------
__device__ __forceinline__ float bilin_sample(const float* __restrict__ s,
                                              float gx, float gy, int H, int W) {
    // torch grid_sample: bilinear, zero padding, align_corners=False
    float x = ((gx + 1.0f) * (float)W - 1.0f) * 0.5f;
    float y = ((gy + 1.0f) * (float)H - 1.0f) * 0.5f;
    float xf = floorf(x), yf = floorf(y);
    int x0 = (int)xf, y0 = (int)yf;
    float wx = x - xf, wy = y - yf;
    int x1 = x0 + 1, y1 = y0 + 1;
    bool xi0 = (x0 >= 0) && (x0 < W);
    bool xi1 = (x1 >= 0) && (x1 < W);
    bool yi0 = (y0 >= 0) && (y0 < H);
    bool yi1 = (y1 >= 0) && (y1 < H);
    float v00 = 0.f, v01 = 0.f, v10 = 0.f, v11 = 0.f;
    if (yi0) {
        const float* row = s + y0 * W;
        if (xi0) v00 = __ldg(row + x0);
        if (xi1) v01 = __ldg(row + x1);
    }
    if (yi1) {
        const float* row = s + y1 * W;
        if (xi0) v10 = __ldg(row + x0);
        if (xi1) v11 = __ldg(row + x1);
    }
    return (1.f - wx) * (1.f - wy) * v00 + wx * (1.f - wy) * v01
         + (1.f - wx) * wy * v10 + wx * wy * v11;
}

// ---------------- K0: 2x3 affine inverses ----------------
__global__ void k_inv(const float* __restrict__ sc, const float* __restrict__ ro,
                      const float* __restrict__ tr) {
    int t = threadIdx.x;
    if (t >= 3 * BN) return;
    int w = t / BN, b = t % BN;
    const float* src = (w == 0) ? sc : ((w == 1) ? ro : tr);
    const float* m = src + b * 6;
    float a = m[0], bb = m[1], c = m[2], d = m[3], e = m[4], f = m[5];
    float det = a * e - bb * d;
    float ia = e / det, ib = -bb / det, id = -d / det, ie = a / det;
    float ic  = -(ia * c + ib * f);
    float iff = -(id * c + ie * f);
    float* o = g_inv + t * 6;
    o[0] = ia; o[1] = ib; o[2] = ic; o[3] = id; o[4] = ie; o[5] = iff;
}

// ---------------- source mask bbox (partials) ----------------
__global__ void k_srcbox(const float* __restrict__ masks) {
    int j = blockIdx.y, seg = blockIdx.x;
    const float* m = masks + j * NPIX;
    int base = seg * (NPIX / 8);
    int rmin = 1 << 20, rmax = -1, cmin = 1 << 20, cmax = -1;
    for (int k = threadIdx.x; k < NPIX / 8; k += TPB) {
        int g = base + k;
        if (m[g] != 0.0f) {
            int r = g >> 9, c = g & 511;
            rmin = min(rmin, r); rmax = max(rmax, r);
            cmin = min(cmin, c); cmax = max(cmax, c);
        }
    }
    __shared__ int s0[TPB], s1[TPB], s2[TPB], s3[TPB];
    s0[threadIdx.x] = rmin; s1[threadIdx.x] = rmax;
    s2[threadIdx.x] = cmin; s3[threadIdx.x] = cmax;
    __syncthreads();
    for (int s = TPB / 2; s > 0; s >>= 1) {
        if (threadIdx.x < s) {
            s0[threadIdx.x] = min(s0[threadIdx.x], s0[threadIdx.x + s]);
            s1[threadIdx.x] = max(s1[threadIdx.x], s1[threadIdx.x + s]);
            s2[threadIdx.x] = min(s2[threadIdx.x], s2[threadIdx.x + s]);
            s3[threadIdx.x] = max(s3[threadIdx.x], s3[threadIdx.x + s]);
        }
        __syncthreads();
    }
    if (threadIdx.x == 0)
        g_srcpart[j * 8 + seg] = make_int4(s0[0], s1[0], s2[0], s3[0]);
}

// ---------------- affine preimage of a pixel rect ----------------
__device__ __forceinline__ void preimage_px(const float* th,
        float ya, float yb, float xa, float xb,
        int& ir0, int& ir1, int& ic0, int& ic1) {
    float gxa = (2.f * xa + 1.f) / 512.f - 1.f, gxb = (2.f * xb + 1.f) / 512.f - 1.f;
    float gya = (2.f * ya + 1.f) / 512.f - 1.f, gyb = (2.f * yb + 1.f) / 512.f - 1.f;
    float det = th[0] * th[4] - th[1] * th[3];
    float Xmin = 1e30f, Xmax = -1e30f, Ymin = 1e30f, Ymax = -1e30f;
    #pragma unroll
    for (int u = 0; u < 4; u++) {
        float gx = (u & 1) ? gxb : gxa;
        float gy = (u & 2) ? gyb : gya;
        float rx = gx - th[2], ry = gy - th[5];
        float X = ( th[4] * rx - th[1] * ry) / det;
        float Y = (-th[3] * rx + th[0] * ry) / det;
        Xmin = fminf(Xmin, X); Xmax = fmaxf(Xmax, X);
        Ymin = fminf(Ymin, Y); Ymax = fmaxf(Ymax, Y);
    }
    float jmin = ((Xmin + 1.f) * 512.f - 1.f) * 0.5f;
    float jmax = ((Xmax + 1.f) * 512.f - 1.f) * 0.5f;
    float imin = ((Ymin + 1.f) * 512.f - 1.f) * 0.5f;
    float imax = ((Ymax + 1.f) * 512.f - 1.f) * 0.5f;
    ir0 = max(0,   (int)floorf(imin) - 1);
    ir1 = min(511, (int)ceilf(imax) + 1);
    ic0 = max(0,   (int)floorf(jmin) - 1);
    ic1 = min(511, (int)ceilf(jmax) + 1);
}

// ---------------- per-(j,b) output boxes (needs g_inv + g_srcpart) ----------------
__global__ void k_boxes() {
    int t = threadIdx.x;
    if (t >= NM * BN) return;
    int j = t / BN, b = t % BN;
    int r0 = 1 << 20, r1 = -1, c0 = 1 << 20, c1 = -1;
    for (int k = 0; k < 8; k++) {
        int4 p = g_srcpart[j * 8 + k];
        r0 = min(r0, p.x); r1 = max(r1, p.y);
        c0 = min(c0, p.z); c1 = max(c1, p.w);
    }
    if (r1 < r0) {
        g_box1[t] = make_int4(0, 0, 0, 0);
        g_box2[t] = make_int4(0, 0, 0, 0);
        return;
    }
    int a0, a1, b0, b1;
    preimage_px(g_inv + (BN + b) * 6,
                (float)r0 - 1.f, (float)r1 + 1.f,
                (float)c0 - 1.f, (float)c1 + 1.f, a0, a1, b0, b1);
    int w0 = max(0, a0 - 2), w1 = min(511, a1 + 2);
    int w2 = max(0, b0 - 2), w3 = min(511, b1 + 2);
    g_box1[t] = make_int4(w0, w2, w1 - w0 + 1, w3 - w2 + 1);
    int d0, d1, e0, e1;
    preimage_px(g_inv + b * 6,
                (float)a0 - 1.f, (float)a1 + 1.f,
                (float)b0 - 1.f, (float)b1 + 1.f, d0, d1, e0, e1);
    d0 = max(0, d0 - 1); d1 = min(511, d1 + 1);
    e0 = max(0, e0 - 1); e1 = min(511, e1 + 1);
    g_box2[t] = make_int4(d0, e0, d1 - d0 + 1, e1 - e0 + 1);
}

// ---------------- K1: jax.image.resize linear, 4 outputs/thread ----------------
__global__ void k_resize4(const float* __restrict__ base, float* __restrict__ out) {
    int idx = blockIdx.x * blockDim.x + threadIdx.x;
    if (idx >= BN * NPIX / 4) return;
    int b = idx / (NPIX / 4), r4 = idx - b * (NPIX / 4);
    int i = r4 >> 7;
    int j0 = (r4 & 127) * 4;
    float fy = (i + 0.5f) * 0.25f - 0.5f;
    fy = fminf(fmaxf(fy, 0.f), 127.f);
    int y0 = (int)fy;
    float wy = fy - (float)y0;
    int y1 = min(y0 + 1, 127);
    const float* p = base + b * 128 * 128;
    const float* r0 = p + y0 * 128;
    const float* r1 = p + y1 * 128;
    float4 o;
    #pragma unroll
    for (int q = 0; q < 4; q++) {
        float fx = (j0 + q + 0.5f) * 0.25f - 0.5f;
        fx = fminf(fmaxf(fx, 0.f), 127.f);
        int x0 = (int)fx;
        float wx = fx - (float)x0;
        int x1 = min(x0 + 1, 127);
        float top = (1.f - wx) * __ldg(r0 + x0) + wx * __ldg(r0 + x1);
        float bot = (1.f - wx) * __ldg(r1 + x0) + wx * __ldg(r1 + x1);
        ((float*)&o)[q] = (1.f - wy) * top + wy * bot;
    }
    ((float4*)out)[idx] = o;
}

// ---------------- image warp, 2D-tiled, 4 px/thread (measured-best shape) ----------------
__global__ void k_warp4t(const float* __restrict__ src, float* __restrict__ dst,
                         float* __restrict__ dst2, int thoff) {
    int b = blockIdx.z;
    int i = blockIdx.y * 8 + threadIdx.y;
    int j0 = (blockIdx.x * 32 + threadIdx.x) * 4;
    const float* th = g_inv + (thoff + b) * 6;
    float t0 = th[0], t1 = th[1], t2 = th[2], t3 = th[3], t4 = th[4], t5 = th[5];
    float Y = (float)(2 * i + 1) / 512.0f - 1.0f;
    const float* s = src + b * NPIX;
    float4 o;
    #pragma unroll
    for (int q = 0; q < 4; q++) {
        float X = (float)(2 * (j0 + q) + 1) / 512.0f - 1.0f;
        float gx = t0 * X + t1 * Y + t2;
        float gy = t3 * X + t4 * Y + t5;
        ((float*)&o)[q] = bilin_sample(s, gx, gy, UPD, UPD);
    }
    int idx4 = (b * NPIX + (i << 9) + j0) >> 2;
    ((float4*)dst)[idx4] = o;
    if (dst2) ((float4*)dst2)[idx4] = o;
}

// ---------------- mask stage 1 (box-restricted, side stream) ----------------
__global__ void k_mask1(const float* __restrict__ masks) {
    int jb = blockIdx.y;
    int j = jb / BN, b = jb % BN;
    int4 bx = g_box1[jb];
    int area = bx.z * bx.w;
    const float* th = g_inv + (BN + b) * 6;
    float t0 = th[0], t1 = th[1], t2 = th[2], t3 = th[3], t4 = th[4], t5 = th[5];
    const float* s = masks + j * NPIX;
    float* dst = g_rm2 + (size_t)jb * NPIX;
    for (int t = blockIdx.x * TPB + threadIdx.x; t < area; t += 8 * TPB) {
        int i = bx.x + t / bx.w, jj = bx.y + t % bx.w;
        float X = (float)(2 * jj + 1) / 512.0f - 1.0f;
        float Y = (float)(2 * i + 1) / 512.0f - 1.0f;
        float gx = t0 * X + t1 * Y + t2;
        float gy = t3 * X + t4 * Y + t5;
        dst[(i << 9) + jj] = bilin_sample(s, gx, gy, UPD, UPD);
    }
}

// ---------------- FUSED mask stage 2 + threshold + COM: one block per (j,b) ----------------
__global__ void k_mask23(const float* __restrict__ img_all, float* __restrict__ mrot) {
    int jb = blockIdx.x;
    int b = jb % BN;
    int tid = threadIdx.x;
    const int NT = 1024;
    __shared__ float sh1[NT], sh2[NT], sh3[NT];
    __shared__ float sh_thr;

    int4 bx = g_box2[jb];
    int area = bx.z * bx.w;
    const float* th = g_inv + b * 6;
    float t0 = th[0], t1 = th[1], t2 = th[2], t3 = th[3], t4 = th[4], t5 = th[5];
    const float* src = g_rm2 + (size_t)jb * NPIX;
    const float* img = img_all + b * NPIX;
    float* dst = mrot + (size_t)jb * NPIX;
    float sn = 0.f, sm = 0.f;
    for (int t = tid; t < area; t += NT) {
        int i = bx.x + t / bx.w, jj = bx.y + t % bx.w;
        float X = (float)(2 * jj + 1) / 512.0f - 1.0f;
        float Y = (float)(2 * i + 1) / 512.0f - 1.0f;
        float gx = t0 * X + t1 * Y + t2;
        float gy = t3 * X + t4 * Y + t5;
        float v = bilin_sample(src, gx, gy, UPD, UPD);
        int g = (i << 9) + jj;
        bool on = (v >= 0.5f);
        dst[g] = on ? 1.0f : 0.0f;
        if (on) { sn += img[g]; sm += 1.0f; }
    }
    sh1[tid] = sn; sh2[tid] = sm;
    __syncthreads();
    for (int s = NT / 2; s > 0; s >>= 1) {
        if (tid < s) { sh1[tid] += sh1[tid + s]; sh2[tid] += sh2[tid + s]; }
        __syncthreads();
    }
    if (tid == 0) sh_thr = (sh1[0] / fmaxf(sh2[0], 1.0f)) * 1.5f;
    __syncthreads();
    float thr = sh_thr;

    float st = 0.f, sx = 0.f, sy = 0.f;
    for (int t = tid; t < area; t += NT) {
        int i = bx.x + t / bx.w, jj = bx.y + t % bx.w;
        int g = (i << 9) + jj;
        if (dst[g] > 0.5f) {
            float nv = img[g];
            if (nv > thr) {
                st += nv;
                sx += nv * (float)i;
                sy += nv * (float)jj;
            }
        }
    }
    sh1[tid] = st; sh2[tid] = sx; sh3[tid] = sy;
    __syncthreads();
    for (int s = NT / 2; s > 0; s >>= 1) {
        if (tid < s) {
            sh1[tid] += sh1[tid + s];
            sh2[tid] += sh2[tid + s];
            sh3[tid] += sh3[tid + s];
        }
        __syncthreads();
    }
    if (tid == 0) {
        g_com[jb * 3 + 0] = sh1[0];
        g_com[jb * 3 + 1] = sh2[0];
        g_com[jb * 3 + 2] = sh3[0];
    }
}

// ---------------- revise: one block per batch item; patch in dynamic smem ----------------
__global__ void k_revise(float* __restrict__ rev, const float* __restrict__ adj) {
    extern __shared__ float patch[];   // PATCH*PATCH floats = 57.6KB
    int b = blockIdx.x;
    int tid = threadIdx.x;
    float a = adj[b];
    float* img = rev + b * NPIX;
    const float* th = g_inv + b * 6;  // inv(scaler_shear)
    __shared__ int sh_xy[2];
    for (int j = 0; j < NM; j++) {
        if (tid == 0) {
            int o = (j * BN + b) * 3;
            float tot = g_com[o] + 1e-8f;
            float cx = g_com[o + 1] / tot, cy = g_com[o + 2] / tot;
            int x0 = __float2int_rn(cx) - 60;            // round half to even
            int y0 = __float2int_rn(cy) - 60;
            x0 = min(max(x0, 0), UPD - PATCH);           // dynamic_slice clamping
            y0 = min(max(y0, 0), UPD - PATCH);
            sh_xy[0] = x0; sh_xy[1] = y0;
        }
        __syncthreads();
        int x0 = sh_xy[0], y0 = sh_xy[1];
        for (int t = tid; t < PATCH * PATCH; t += blockDim.x) {
            int p = t / PATCH, q = t - p * PATCH;
            float v = img[(x0 + p) * UPD + (y0 + q)];
            int dp = p - 60, dq = q - 60;
            if (dp * dp + dq * dq <= 16) v = v / a;
            patch[t] = v;
        }
        __syncthreads();
        for (int t = tid; t < PATCH * PATCH; t += blockDim.x) {
            int p = t / PATCH, q = t - p * PATCH;
            float X = (float)(2 * q + 1) / 120.0f - 1.0f;
            float Y = (float)(2 * p + 1) / 120.0f - 1.0f;
            float gx = th[0] * X + th[1] * Y + th[2];
            float gy = th[3] * X + th[4] * Y + th[5];
            float x = ((gx + 1.0f) * 120.0f - 1.0f) * 0.5f;
            float y = ((gy + 1.0f) * 120.0f - 1.0f) * 0.5f;
            float xf = floorf(x), yf = floorf(y);
            int xx0 = (int)xf, yy0 = (int)yf;
            float wx = x - xf, wy = y - yf;
            int xx1 = xx0 + 1, yy1 = yy0 + 1;
            bool xi0 = (xx0 >= 0) && (xx0 < PATCH);
            bool xi1 = (xx1 >= 0) && (xx1 < PATCH);
            bool yi0 = (yy0 >= 0) && (yy0 < PATCH);
            bool yi1 = (yy1 >= 0) && (yy1 < PATCH);
            float v00 = (yi0 && xi0) ? patch[yy0 * PATCH + xx0] : 0.f;
            float v01 = (yi0 && xi1) ? patch[yy0 * PATCH + xx1] : 0.f;
            float v10 = (yi1 && xi0) ? patch[yy1 * PATCH + xx0] : 0.f;
            float v11 = (yi1 && xi1) ? patch[yy1 * PATCH + xx1] : 0.f;
            float v = (1.f - wx) * (1.f - wy) * v00 + wx * (1.f - wy) * v01
                    + (1.f - wx) * wy * v10 + wx * wy * v11;
            img[(x0 + p) * UPD + (y0 + q)] = v;
        }
        __syncthreads();
    }
}

// ---------------- launch ----------------
extern "C" void kernel_launch(void* const* d_in, const int* in_sizes, int n_in,
                              void* d_out, int out_size) {
    const float* base  = (const float*)d_in[0];
    const float* sc    = (const float*)d_in[1];
    const float* ro    = (const float*)d_in[2];
    const float* tr    = (const float*)d_in[3];
    const float* adj   = (const float*)d_in[4];
    const float* masks = (const float*)d_in[5];
    float* out = (float*)d_out;
    float* seg0 = out;                           // base_inp
    float* seg1 = out + (size_t)BN * NPIX;       // pred_input
    float* seg2 = out + (size_t)2 * BN * NPIX;   // pred_revise
    float* seg3 = out + (size_t)3 * BN * NPIX;   // masks_rot

    float *bufA, *bufB;
    cudaGetSymbolAddress((void**)&bufA, g_bufA);
    cudaGetSymbolAddress((void**)&bufB, g_bufB);

    // One-time resource setup on the FIRST (uncaptured) call; reused during
    // capture so no driver allocations occur inside the graph lifetime.
    static cudaStream_t s1 = nullptr;
    static cudaEvent_t evRoot, evInv, evS1;
    static bool init_done = false;
    if (!init_done) {
        cudaFuncSetAttribute(k_revise, cudaFuncAttributeMaxDynamicSharedMemorySize,
                             PATCH * PATCH * (int)sizeof(float));
        cudaStreamCreateWithFlags(&s1, cudaStreamNonBlocking);
        cudaEventCreateWithFlags(&evRoot, cudaEventDisableTiming);
        cudaEventCreateWithFlags(&evInv, cudaEventDisableTiming);
        cudaEventCreateWithFlags(&evS1, cudaEventDisableTiming);
        init_done = true;
    }

    int nblk_img4 = (BN * NPIX / 4 + TPB - 1) / TPB;
    dim3 wgrid4(4, 64, BN), wblk(32, 8);

    // fork
    cudaEventRecord(evRoot, 0);
    cudaStreamWaitEvent(s1, evRoot, 0);

    // main chain (default stream)
    k_inv<<<1, 64>>>(sc, ro, tr);
    cudaEventRecord(evInv, 0);
    k_resize4<<<nblk_img4, TPB>>>(base, seg0);
    k_warp4t<<<wgrid4, wblk>>>(seg0, bufA, nullptr, 2 * BN);    // inv(translation)
    k_warp4t<<<wgrid4, wblk>>>(bufA, bufB, nullptr, 1 * BN);    // inv(rotation)
    k_warp4t<<<wgrid4, wblk>>>(bufB, seg1, seg2, 0);            // inv(shear)

    // side branch s1: memset + srcbox + boxes + mask1 (independent of image chain)
    cudaMemsetAsync(seg3, 0, (size_t)NM * BN * NPIX * sizeof(float), s1);
    k_srcbox<<<dim3(8, NM), TPB, 0, s1>>>(masks);
    cudaStreamWaitEvent(s1, evInv, 0);
    k_boxes<<<1, 64, 0, s1>>>();
    k_mask1<<<dim3(8, NM * BN), TPB, 0, s1>>>(masks);
    cudaEventRecord(evS1, s1);

    // join, fused mask stage2+COM, revise
    cudaStreamWaitEvent(0, evS1, 0);
    k_mask23<<<NM * BN, 1024>>>(seg1, seg3);
    k_revise<<<BN, 1024, PATCH * PATCH * sizeof(float)>>>(seg2, adj);
}